// round 13
// baseline (speedup 1.0000x reference)
#include <cuda_runtime.h>
#include <cuda_bf16.h>
#include <cstdint>
#include <cstddef>

#define HN  8
#define DM  512
#define DKH 64
#define BB  8
#define SS  1024
#define MR  (BB * SS)
#define SL  ((size_t)MR * DM)
#define EL  ((size_t)MR * DM)
#define WEL ((size_t)DM * DM)

__device__ __nv_bfloat16 g_bf[24 * EL + 16 * WEL];
__device__ float g_stats[4 * (size_t)65536];

// ---------------------------------------------------------------------------
__device__ __forceinline__ uint32_t smem_u32(const void* p) {
    uint32_t a;
    asm("{ .reg .u64 t; cvta.to.shared.u64 t, %1; cvt.u32.u64 %0, t; }" : "=r"(a) : "l"(p));
    return a;
}
__device__ __forceinline__ void ldmx4(uint32_t* r, uint32_t a) {
    asm volatile("ldmatrix.sync.aligned.m8n8.x4.shared.b16 {%0,%1,%2,%3}, [%4];"
                 : "=r"(r[0]), "=r"(r[1]), "=r"(r[2]), "=r"(r[3]) : "r"(a));
}
__device__ __forceinline__ void ldmx2(uint32_t* r, uint32_t a) {
    asm volatile("ldmatrix.sync.aligned.m8n8.x2.shared.b16 {%0,%1}, [%2];"
                 : "=r"(r[0]), "=r"(r[1]) : "r"(a));
}
__device__ __forceinline__ void mma16816(float* c, const uint32_t* a,
                                         uint32_t b0, uint32_t b1) {
    asm volatile(
        "mma.sync.aligned.m16n8k16.row.col.f32.bf16.bf16.f32 "
        "{%0,%1,%2,%3}, {%4,%5,%6,%7}, {%8,%9}, {%0,%1,%2,%3};"
        : "+f"(c[0]), "+f"(c[1]), "+f"(c[2]), "+f"(c[3])
        : "r"(a[0]), "r"(a[1]), "r"(a[2]), "r"(a[3]), "r"(b0), "r"(b1));
}
__device__ __forceinline__ void cp16(uint32_t dst, const void* src) {
    asm volatile("cp.async.cg.shared.global [%0], [%1], 16;" :: "r"(dst), "l"(src));
}
__device__ __forceinline__ void cp_commit() {
    asm volatile("cp.async.commit_group;" ::: "memory");
}
template <int N>
__device__ __forceinline__ void cp_wait() {
    asm volatile("cp.async.wait_group %0;" :: "n"(N) : "memory");
}
__device__ __forceinline__ uint32_t pkbf2(float x, float y) {
    __nv_bfloat162 t;
    t.x = __float2bfloat16_rn(x);
    t.y = __float2bfloat16_rn(y);
    return *reinterpret_cast<uint32_t*>(&t);
}
__device__ __forceinline__ void split4(float4 v, uint2& hi, uint2& lo) {
    __nv_bfloat16 hx = __float2bfloat16_rn(v.x);
    __nv_bfloat16 hy = __float2bfloat16_rn(v.y);
    __nv_bfloat16 hz = __float2bfloat16_rn(v.z);
    __nv_bfloat16 hw = __float2bfloat16_rn(v.w);
    float rx = v.x - __bfloat162float(hx);
    float ry = v.y - __bfloat162float(hy);
    float rz = v.z - __bfloat162float(hz);
    float rw = v.w - __bfloat162float(hw);
    __nv_bfloat162 h01; h01.x = hx; h01.y = hy;
    __nv_bfloat162 h23; h23.x = hz; h23.y = hw;
    hi.x = *reinterpret_cast<uint32_t*>(&h01);
    hi.y = *reinterpret_cast<uint32_t*>(&h23);
    lo.x = pkbf2(rx, ry);
    lo.y = pkbf2(rz, rw);
}
__device__ __forceinline__ void splitp2(float x, float y, uint32_t& hi, uint32_t& lo) {
    __nv_bfloat16 hx = __float2bfloat16_rn(x);
    __nv_bfloat16 hy = __float2bfloat16_rn(y);
    __nv_bfloat162 h; h.x = hx; h.y = hy;
    hi = *reinterpret_cast<uint32_t*>(&h);
    lo = pkbf2(x - __bfloat162float(hx), y - __bfloat162float(hy));
}

// ---------------------------------------------------------------------------
// One-shot fp32 -> split-bf16 conversion (inputs + weights).
// ---------------------------------------------------------------------------
struct CvtJobs {
    const float* src[10];
    __nv_bfloat16* hi[10];
    __nv_bfloat16* lo[10];
    int n4[10];
};
__global__ void __launch_bounds__(256) cvt_split(CvtJobs J) {
    const int j = blockIdx.y;
    const int idx = blockIdx.x * 256 + threadIdx.x;
    if (idx >= J.n4[j]) return;
    float4 v = ((const float4*)J.src[j])[idx];
    uint2 hi, lo;
    split4(v, hi, lo);
    ((uint2*)J.hi[j])[idx] = hi;
    ((uint2*)J.lo[j])[idx] = lo;
}

// ---------------------------------------------------------------------------
// Split-bf16 NT GEMM, preconverted operands, cp.async double-buffered.
// 256 threads, 8 warps (2x4), warp tile 64x32 (LDS/MMA ratio 0.5).
// Register-lean fragment streaming (B via x2 per-kk, A per-(mb,kk)) +
// __launch_bounds__(256,2) -> 2 CTAs/SM = 16 warps/SM.
// ---------------------------------------------------------------------------
template <int NZ>
struct PArgs {
    const __nv_bfloat16 *aH[NZ], *aL[NZ], *bH[NZ], *bL[NZ];
    const float* bias[NZ];
    __nv_bfloat16 *oH[NZ], *oL[NZ];
    float* C[NZ];
};

template <int NZ, bool OUTBF>
__global__ void __launch_bounds__(256, 2) proj_gemm(PArgs<NZ> P)
{
    extern __shared__ char sm[];
    const uint32_t sb = smem_u32(sm);
    const int tid = threadIdx.x, lane = tid & 31, warp = tid >> 5;
    const int z = blockIdx.z;
    const int m0 = blockIdx.y * 128, n0 = blockIdx.x * 128;

    const __nv_bfloat16* AH = P.aH[z] + (size_t)m0 * DM;
    const __nv_bfloat16* AL = P.aL[z] + (size_t)m0 * DM;
    const __nv_bfloat16* BH = P.bH[z] + (size_t)n0 * DM;
    const __nv_bfloat16* BL = P.bL[z] + (size_t)n0 * DM;

    // loader: 2 chunks per plane per thread per stage (8 cp16)
    auto issue = [&](int buf, int k0) {
        const uint32_t base = sb + buf * 32768;
#pragma unroll
        for (int jj = 0; jj < 8; jj++) {
            const int comp = jj >> 1;
            const int ci = tid + 256 * (jj & 1);
            const int row = ci >> 2, ch = ci & 3;
            const uint32_t dst = base + comp * 8192 + row * 64
                                 + ((uint32_t)(ch ^ (row & 3)) << 4);
            const __nv_bfloat16* sp = (comp == 0 ? AH : comp == 1 ? AL
                                       : comp == 2 ? BH : BL);
            cp16(dst, sp + (size_t)row * DM + k0 + ch * 8);
        }
        cp_commit();
    };

    const int wm = warp & 1, wn = warp >> 1;       // 2 x 4 warp grid, 64x32 tile
    const int cHi = lane >> 4;                     // A x4 chunk selector
    uint32_t rowAoff[4]; int rA3[4];
#pragma unroll
    for (int mb = 0; mb < 4; mb++) {
        const int rowA = wm * 64 + mb * 16 + (lane & 15);
        rowAoff[mb] = rowA * 64;
        rA3[mb] = rowA & 3;
    }
    // B x2 addressing: lanes 0..15 supply 2 matrices (chunk 2kk+bsel)
    const int bsel = (lane >> 3) & 1;
    uint32_t addrB[4]; int rB3[4];
#pragma unroll
    for (int nb = 0; nb < 4; nb++) {
        const int rowB = wn * 32 + nb * 8 + (lane & 7);
        addrB[nb] = rowB * 64;
        rB3[nb] = rowB & 3;
    }

    float acc[4][4][4];
#pragma unroll
    for (int mb = 0; mb < 4; mb++)
#pragma unroll
        for (int nb = 0; nb < 4; nb++)
#pragma unroll
            for (int r = 0; r < 4; r++) acc[mb][nb][r] = 0.f;

    issue(0, 0);

    const int NSTG = 16;
    for (int s = 0; s < NSTG; s++) {
        if (s + 1 < NSTG) {
            issue((s + 1) & 1, (s + 1) * 32);
            cp_wait<1>();
        } else {
            cp_wait<0>();
        }
        __syncthreads();

        const uint32_t stb = sb + (s & 1) * 32768;
#pragma unroll
        for (int kk = 0; kk < 2; kk++) {
            uint32_t BH2[4][2], BL2[4][2];
#pragma unroll
            for (int nb = 0; nb < 4; nb++) {
                const uint32_t a = stb + 16384 + addrB[nb]
                                   + ((uint32_t)((2 * kk + bsel) ^ rB3[nb]) << 4);
                ldmx2(BH2[nb], a);
                ldmx2(BL2[nb], a + 8192);
            }
#pragma unroll
            for (int mb = 0; mb < 4; mb++) {
                const uint32_t a = stb + rowAoff[mb]
                                   + ((uint32_t)((2 * kk + cHi) ^ rA3[mb]) << 4);
                uint32_t AHf[4], ALf[4];
                ldmx4(AHf, a);
                ldmx4(ALf, a + 8192);
#pragma unroll
                for (int nb = 0; nb < 4; nb++) {
                    mma16816(acc[mb][nb], AHf, BH2[nb][0], BH2[nb][1]);
                    mma16816(acc[mb][nb], AHf, BL2[nb][0], BL2[nb][1]);
                    mma16816(acc[mb][nb], ALf, BH2[nb][0], BH2[nb][1]);
                }
            }
        }
        __syncthreads();
    }

    const int gr = lane >> 2, gc2 = (lane & 3) * 2;
#pragma unroll
    for (int mb = 0; mb < 4; mb++) {
        const int row = m0 + wm * 64 + mb * 16 + gr;
#pragma unroll
        for (int nb = 0; nb < 4; nb++) {
            const int gcol = n0 + wn * 32 + nb * 8 + gc2;
            const float bx = P.bias[z][gcol], by = P.bias[z][gcol + 1];
            const float v0 = acc[mb][nb][0] + bx, v1 = acc[mb][nb][1] + by;
            const float v2 = acc[mb][nb][2] + bx, v3 = acc[mb][nb][3] + by;
            if (OUTBF) {
                uint32_t h, l;
                splitp2(v0, v1, h, l);
                *(uint32_t*)(P.oH[z] + (size_t)row * DM + gcol) = h;
                *(uint32_t*)(P.oL[z] + (size_t)row * DM + gcol) = l;
                splitp2(v2, v3, h, l);
                *(uint32_t*)(P.oH[z] + (size_t)(row + 8) * DM + gcol) = h;
                *(uint32_t*)(P.oL[z] + (size_t)(row + 8) * DM + gcol) = l;
            } else {
                float* C = P.C[z];
                *(float2*)(C + (size_t)row * DM + gcol) = make_float2(v0, v1);
                *(float2*)(C + (size_t)(row + 8) * DM + gcol) = make_float2(v2, v3);
            }
        }
    }
}

// ---------------------------------------------------------------------------
// Per-head split-bf16 V transpose (both streams; zz = stream*64 + z).
// ---------------------------------------------------------------------------
__global__ void __launch_bounds__(256) transpose_v_bf(
    const __nv_bfloat16* vrH, const __nv_bfloat16* vrL,
    const __nv_bfloat16* vfH, const __nv_bfloat16* vfL,
    __nv_bfloat16* vtrH, __nv_bfloat16* vtrL,
    __nv_bfloat16* vtfH, __nv_bfloat16* vtfL)
{
    __shared__ unsigned short t[2][32][33];
    const int zz = blockIdx.z;
    const int str = zz >> 6, z = zz & 63;
    const int zbv = z >> 3, zhv = z & 7;
    const int s0 = blockIdx.x * 32, d0 = blockIdx.y * 32;
    const unsigned short* sH = (const unsigned short*)((str ? vfH : vrH)
                               + (size_t)zbv * SS * DM + zhv * 64);
    const unsigned short* sL = (const unsigned short*)((str ? vfL : vrL)
                               + (size_t)zbv * SS * DM + zhv * 64);
    unsigned short* dH = (unsigned short*)((str ? vtfH : vtrH) + (size_t)z * DKH * SS);
    unsigned short* dL = (unsigned short*)((str ? vtfL : vtrL) + (size_t)z * DKH * SS);
    const int tx = threadIdx.x, ty = threadIdx.y;
    for (int i = ty; i < 32; i += 8) {
        t[0][i][tx] = sH[(size_t)(s0 + i) * DM + d0 + tx];
        t[1][i][tx] = sL[(size_t)(s0 + i) * DM + d0 + tx];
    }
    __syncthreads();
    for (int i = ty; i < 32; i += 8) {
        dH[(size_t)(d0 + i) * SS + s0 + tx] = t[0][tx][i];
        dL[(size_t)(d0 + i) * SS + s0 + tx] = t[1][tx][i];
    }
}

// ---------------------------------------------------------------------------
// cp.async tile stagers (pure copies, swizzled dst).
// ---------------------------------------------------------------------------
__device__ __forceinline__ void cp_tile_rk(uint32_t dh, uint32_t dl,
                                           const __nv_bfloat16* sh,
                                           const __nv_bfloat16* sl, int tid) {
#pragma unroll
    for (int jj = 0; jj < 8; jj++) {
        const int comp = jj >> 2;
        const int ci = tid + 256 * (jj & 3);
        const int row = ci >> 3, ch = ci & 7;
        const uint32_t dst = (comp ? dl : dh) + row * 128
                             + ((uint32_t)(ch ^ (row & 7)) << 4);
        const __nv_bfloat16* src = (comp ? sl : sh);
        cp16(dst, src + (size_t)row * DM + ch * 8);
    }
}
__device__ __forceinline__ void cp_tile_vt(uint32_t dh, uint32_t dl,
                                           const __nv_bfloat16* sh,
                                           const __nv_bfloat16* sl, int tid) {
#pragma unroll
    for (int jj = 0; jj < 8; jj++) {
        const int comp = jj >> 2;
        const int ci = tid + 256 * (jj & 3);
        const int row = ci >> 4, ch = ci & 15;
        const uint32_t dst = (comp ? dl : dh) + row * 256
                             + ((uint32_t)(ch ^ (row & 7)) << 4);
        const __nv_bfloat16* src = (comp ? sl : sh);
        cp16(dst, src + (size_t)row * SS + ch * 8);
    }
}

// S chunk: one warp, 16 q rows x 64 kv cols (cols g*64..+63), full dk=64.
__device__ __forceinline__ void s_tile8(uint32_t qh, uint32_t ql, uint32_t kh, uint32_t kl,
                                        int wr0, int lane, int g, float c[8][4]) {
#pragma unroll
    for (int j = 0; j < 8; j++) { c[j][0] = c[j][1] = c[j][2] = c[j][3] = 0.f; }
    const int ar = wr0 + (lane & 15);
    const uint32_t abase = (uint32_t)ar * 128;
    const int arx = ar & 7;
    const int aC = lane >> 4;
    const int brr = lane & 7, bch = lane >> 3;
#pragma unroll
    for (int half = 0; half < 2; half++) {
        const int cb = half * 4;
        uint32_t AH0[4], AH1[4], AL0[4], AL1[4];
        const uint32_t a0off = abase + ((uint32_t)((cb + aC) ^ arx) << 4);
        const uint32_t a1off = abase + ((uint32_t)((cb + 2 + aC) ^ arx) << 4);
        ldmx4(AH0, qh + a0off);
        ldmx4(AL0, ql + a0off);
        ldmx4(AH1, qh + a1off);
        ldmx4(AL1, ql + a1off);
#pragma unroll
        for (int j = 0; j < 8; j++) {
            const int r = (g * 8 + j) * 8 + brr;
            const uint32_t bb = (uint32_t)r * 128 + ((uint32_t)((cb + bch) ^ (r & 7)) << 4);
            uint32_t BH[4], BL[4];
            ldmx4(BH, kh + bb);
            ldmx4(BL, kl + bb);
            mma16816(c[j], AH0, BH[0], BH[1]);
            mma16816(c[j], AH0, BL[0], BL[1]);
            mma16816(c[j], AL0, BH[0], BH[1]);
            mma16816(c[j], AH1, BH[2], BH[3]);
            mma16816(c[j], AH1, BL[2], BL[3]);
            mma16816(c[j], AL1, BH[2], BH[3]);
        }
    }
}

// ---------------------------------------------------------------------------
// Pass 1: online softmax stats. grid (8 qtiles, 64 z, 2 streams).
// SMEM 96KB -> 2 CTAs/SM.
// ---------------------------------------------------------------------------
struct StatArgs {
    const __nv_bfloat16 *q[2][2], *k[2][2];
    float *M[2], *D[2];
};
__global__ void __launch_bounds__(256) fa_stats(StatArgs A)
{
    extern __shared__ char sm[];
    const uint32_t sb = smem_u32(sm);
    const int tid = threadIdx.x, lane = tid & 31, warp = tid >> 5;
    const int str = blockIdx.z, z = blockIdx.y, zb = z >> 3, zh = z & 7;
    const int q0 = blockIdx.x * 128;

    const __nv_bfloat16* Qh = A.q[str][0] + ((size_t)(zb * SS + q0)) * DM + zh * DKH;
    const __nv_bfloat16* Ql = A.q[str][1] + ((size_t)(zb * SS + q0)) * DM + zh * DKH;
    const __nv_bfloat16* Kh = A.k[str][0] + ((size_t)zb * SS) * DM + zh * DKH;
    const __nv_bfloat16* Kl = A.k[str][1] + ((size_t)zb * SS) * DM + zh * DKH;

    cp_tile_rk(sb, sb + 16384, Qh, Ql, tid);
    cp_commit();
    cp_tile_rk(sb + 32768, sb + 49152, Kh, Kl, tid);
    cp_commit();

    const int wr0 = warp * 16;
    float mr0 = -1e30f, mr1 = -1e30f, dr0 = 0.f, dr1 = 0.f;

    for (int kt = 0; kt < 8; kt++) {
        if (kt + 1 < 8) {
            const uint32_t b = sb + 32768 + ((kt + 1) & 1) * 32768;
            cp_tile_rk(b, b + 16384, Kh + (size_t)(kt + 1) * 128 * DM,
                       Kl + (size_t)(kt + 1) * 128 * DM, tid);
            cp_commit();
            cp_wait<1>();
        } else {
            cp_wait<0>();
        }
        __syncthreads();

        const uint32_t kb = sb + 32768 + (kt & 1) * 32768;
#pragma unroll
        for (int g = 0; g < 2; g++) {
            float c[8][4];
            s_tile8(sb, sb + 16384, kb, kb + 16384, wr0, lane, g, c);
#pragma unroll
            for (int j = 0; j < 8; j++) {
                c[j][0] *= 0.125f; c[j][1] *= 0.125f;
                c[j][2] *= 0.125f; c[j][3] *= 0.125f;
            }
            float m0 = -1e30f, m1 = -1e30f;
#pragma unroll
            for (int j = 0; j < 8; j++) {
                m0 = fmaxf(m0, fmaxf(c[j][0], c[j][1]));
                m1 = fmaxf(m1, fmaxf(c[j][2], c[j][3]));
            }
            m0 = fmaxf(m0, __shfl_xor_sync(0xffffffffu, m0, 1));
            m0 = fmaxf(m0, __shfl_xor_sync(0xffffffffu, m0, 2));
            m1 = fmaxf(m1, __shfl_xor_sync(0xffffffffu, m1, 1));
            m1 = fmaxf(m1, __shfl_xor_sync(0xffffffffu, m1, 2));
            const float M0 = fmaxf(mr0, m0), M1 = fmaxf(mr1, m1);
            float s0 = 0.f, s1 = 0.f;
#pragma unroll
            for (int j = 0; j < 8; j++) {
                s0 += __expf(c[j][0] - M0) + __expf(c[j][1] - M0);
                s1 += __expf(c[j][2] - M1) + __expf(c[j][3] - M1);
            }
            s0 += __shfl_xor_sync(0xffffffffu, s0, 1);
            s0 += __shfl_xor_sync(0xffffffffu, s0, 2);
            s1 += __shfl_xor_sync(0xffffffffu, s1, 1);
            s1 += __shfl_xor_sync(0xffffffffu, s1, 2);
            dr0 = dr0 * __expf(mr0 - M0) + s0; mr0 = M0;
            dr1 = dr1 * __expf(mr1 - M1) + s1; mr1 = M1;
        }
        __syncthreads();
    }

    if ((lane & 3) == 0) {
        const int r0 = q0 + wr0 + (lane >> 2);
        A.M[str][(size_t)z * SS + r0] = mr0;
        A.D[str][(size_t)z * SS + r0] = dr0;
        A.M[str][(size_t)z * SS + r0 + 8] = mr1;
        A.D[str][(size_t)z * SS + r0 + 8] = dr1;
    }
}

// ---------------------------------------------------------------------------
// Pass 2 (round-9 form): recompute S both streams, merged P, dual PV.
// grid (8 qtiles, 64 z). SMEM 192KB: q 4x16K | K 4x16K | V 4x16K.
// ---------------------------------------------------------------------------
__global__ void __launch_bounds__(256) fa_apply(
    const __nv_bfloat16* qrH, const __nv_bfloat16* qrL,
    const __nv_bfloat16* krH, const __nv_bfloat16* krL,
    const __nv_bfloat16* qfH, const __nv_bfloat16* qfL,
    const __nv_bfloat16* kfH, const __nv_bfloat16* kfL,
    const __nv_bfloat16* vtrH, const __nv_bfloat16* vtrL,
    const __nv_bfloat16* vtfH, const __nv_bfloat16* vtfL,
    const float* __restrict__ gMr, const float* __restrict__ gDr,
    const float* __restrict__ gMf, const float* __restrict__ gDf,
    __nv_bfloat16* orH, __nv_bfloat16* orL,
    __nv_bfloat16* ofH, __nv_bfloat16* ofL)
{
    extern __shared__ char sm[];
    const uint32_t sb = smem_u32(sm);
    const int tid = threadIdx.x, lane = tid & 31, warp = tid >> 5;
    const int z = blockIdx.y, zb = z >> 3, zh = z & 7;
    const int q0 = blockIdx.x * 128;

    const size_t qoff = ((size_t)(zb * SS + q0)) * DM + zh * DKH;
    const size_t koff = ((size_t)zb * SS) * DM + zh * DKH;
    const size_t voff = (size_t)z * DKH * SS;

    cp_tile_rk(sb, sb + 16384, qrH + qoff, qrL + qoff, tid);
    cp_tile_rk(sb + 32768, sb + 49152, qfH + qoff, qfL + qoff, tid);
    cp_commit();

    const int wr0 = warp * 16;
    const int gr = lane >> 2;
    const int r0g = q0 + wr0 + gr;
    const size_t st0 = (size_t)z * SS + r0g;
    const float Mr0 = gMr[st0],        Mr1 = gMr[st0 + 8];
    const float iDr0 = 1.f / gDr[st0], iDr1 = 1.f / gDr[st0 + 8];
    const float Mf0 = gMf[st0],        Mf1 = gMf[st0 + 8];
    const float iDf0 = 1.f / gDf[st0], iDf1 = 1.f / gDf[st0 + 8];

    float accR[8][4], accF[8][4];
#pragma unroll
    for (int nb = 0; nb < 8; nb++)
#pragma unroll
        for (int r = 0; r < 4; r++) { accR[nb][r] = 0.f; accF[nb][r] = 0.f; }

    const uint32_t KB = sb + 65536;
    const uint32_t VB = sb + 131072;

    for (int kt = 0; kt < 8; kt++) {
        const size_t kadd = (size_t)kt * 128 * DM;
        cp_tile_rk(KB, KB + 16384, krH + koff + kadd, krL + koff + kadd, tid);
        cp_tile_rk(KB + 32768, KB + 49152, kfH + koff + kadd, kfL + koff + kadd, tid);
        cp_commit();
        cp_tile_vt(VB, VB + 16384, vtrH + voff + kt * 128, vtrL + voff + kt * 128, tid);
        cp_tile_vt(VB + 32768, VB + 49152, vtfH + voff + kt * 128, vtfL + voff + kt * 128, tid);
        cp_commit();
        cp_wait<1>();
        __syncthreads();

        uint32_t ph[8][4], pl[8][4];
#pragma unroll
        for (int g = 0; g < 2; g++) {
            float cr[8][4], cf[8][4];
            s_tile8(sb, sb + 16384, KB, KB + 16384, wr0, lane, g, cr);
            s_tile8(sb + 32768, sb + 49152, KB + 32768, KB + 49152, wr0, lane, g, cf);
#pragma unroll
            for (int jj = 0; jj < 4; jj++) {
                const int kk = g * 4 + jj;
                const int e0 = 2 * jj, e1 = 2 * jj + 1;
                const float p00 = fmaxf(__expf(cr[e0][0] * 0.125f - Mr0) * iDr0,
                                        __expf(cf[e0][0] * 0.125f - Mf0) * iDf0);
                const float p01 = fmaxf(__expf(cr[e0][1] * 0.125f - Mr0) * iDr0,
                                        __expf(cf[e0][1] * 0.125f - Mf0) * iDf0);
                const float p10 = fmaxf(__expf(cr[e0][2] * 0.125f - Mr1) * iDr1,
                                        __expf(cf[e0][2] * 0.125f - Mf1) * iDf1);
                const float p11 = fmaxf(__expf(cr[e0][3] * 0.125f - Mr1) * iDr1,
                                        __expf(cf[e0][3] * 0.125f - Mf1) * iDf1);
                const float q00 = fmaxf(__expf(cr[e1][0] * 0.125f - Mr0) * iDr0,
                                        __expf(cf[e1][0] * 0.125f - Mf0) * iDf0);
                const float q01 = fmaxf(__expf(cr[e1][1] * 0.125f - Mr0) * iDr0,
                                        __expf(cf[e1][1] * 0.125f - Mf0) * iDf0);
                const float q10 = fmaxf(__expf(cr[e1][2] * 0.125f - Mr1) * iDr1,
                                        __expf(cf[e1][2] * 0.125f - Mf1) * iDf1);
                const float q11 = fmaxf(__expf(cr[e1][3] * 0.125f - Mr1) * iDr1,
                                        __expf(cf[e1][3] * 0.125f - Mf1) * iDf1);
                splitp2(p00, p01, ph[kk][0], pl[kk][0]);
                splitp2(p10, p11, ph[kk][1], pl[kk][1]);
                splitp2(q00, q01, ph[kk][2], pl[kk][2]);
                splitp2(q10, q11, ph[kk][3], pl[kk][3]);
            }
        }

        cp_wait<0>();
        __syncthreads();

        const int brr = lane & 7, bch = lane >> 3;
#pragma unroll
        for (int cb = 0; cb < 16; cb += 4) {
            const int kk = cb >> 1;
#pragma unroll
            for (int nb = 0; nb < 8; nb++) {
                const int r = nb * 8 + brr;
                const uint32_t bb = (uint32_t)r * 256
                                    + ((uint32_t)((cb + bch) ^ (r & 7)) << 4);
                uint32_t BHf[4], BLf[4];
                ldmx4(BHf, VB + bb);
                ldmx4(BLf, VB + 16384 + bb);
                mma16816(accR[nb], ph[kk], BHf[0], BHf[1]);
                mma16816(accR[nb], pl[kk], BHf[0], BHf[1]);
                mma16816(accR[nb], ph[kk], BLf[0], BLf[1]);
                mma16816(accR[nb], ph[kk + 1], BHf[2], BHf[3]);
                mma16816(accR[nb], pl[kk + 1], BHf[2], BHf[3]);
                mma16816(accR[nb], ph[kk + 1], BLf[2], BLf[3]);
                ldmx4(BHf, VB + 32768 + bb);
                ldmx4(BLf, VB + 49152 + bb);
                mma16816(accF[nb], ph[kk], BHf[0], BHf[1]);
                mma16816(accF[nb], pl[kk], BHf[0], BHf[1]);
                mma16816(accF[nb], ph[kk], BLf[0], BLf[1]);
                mma16816(accF[nb], ph[kk + 1], BHf[2], BHf[3]);
                mma16816(accF[nb], pl[kk + 1], BHf[2], BHf[3]);
                mma16816(accF[nb], ph[kk + 1], BLf[2], BLf[3]);
            }
        }
        __syncthreads();
    }

    const int gc2 = (lane & 3) * 2;
    const size_t ro0 = ((size_t)(zb * SS + r0g)) * DM + zh * DKH;
    const size_t ro1 = ro0 + (size_t)8 * DM;
#pragma unroll
    for (int nb = 0; nb < 8; nb++) {
        const int col = nb * 8 + gc2;
        uint32_t h, l;
        splitp2(accR[nb][0], accR[nb][1], h, l);
        *(uint32_t*)(orH + ro0 + col) = h;
        *(uint32_t*)(orL + ro0 + col) = l;
        splitp2(accR[nb][2], accR[nb][3], h, l);
        *(uint32_t*)(orH + ro1 + col) = h;
        *(uint32_t*)(orL + ro1 + col) = l;
        splitp2(accF[nb][0], accF[nb][1], h, l);
        *(uint32_t*)(ofH + ro0 + col) = h;
        *(uint32_t*)(ofL + ro0 + col) = l;
        splitp2(accF[nb][2], accF[nb][3], h, l);
        *(uint32_t*)(ofH + ro1 + col) = h;
        *(uint32_t*)(ofL + ro1 + col) = l;
    }
}

// ---------------------------------------------------------------------------
extern "C" void kernel_launch(void* const* d_in, const int* in_sizes, int n_in,
                              void* d_out, int out_size)
{
    const float* rgb  = (const float*)d_in[0];
    const float* flow = (const float*)d_in[1];
    const float* W[8] = {(const float*)d_in[2],  (const float*)d_in[4],
                         (const float*)d_in[6],  (const float*)d_in[8],
                         (const float*)d_in[10], (const float*)d_in[12],
                         (const float*)d_in[14], (const float*)d_in[16]};
    const float* Bv[8] = {(const float*)d_in[3],  (const float*)d_in[5],
                          (const float*)d_in[7],  (const float*)d_in[9],
                          (const float*)d_in[11], (const float*)d_in[13],
                          (const float*)d_in[15], (const float*)d_in[17]};

    __nv_bfloat16* bf = nullptr;
    float* stats = nullptr;
    cudaGetSymbolAddress((void**)&bf, g_bf);
    cudaGetSymbolAddress((void**)&stats, g_stats);

    auto plane = [&](int i) { return bf + (size_t)i * EL; };
    __nv_bfloat16* wbase = bf + 24 * EL;
    auto wH = [&](int i) { return wbase + (size_t)i * 2 * WEL; };
    auto wL = [&](int i) { return wbase + (size_t)i * 2 * WEL + WEL; };

    float* mR = stats;
    float* dR = stats + 65536;
    float* mF = stats + 2 * (size_t)65536;
    float* dF = stats + 3 * (size_t)65536;

    CvtJobs J;
    J.src[0] = rgb;  J.hi[0] = plane(0); J.lo[0] = plane(1); J.n4[0] = (int)(EL / 4);
    J.src[1] = flow; J.hi[1] = plane(2); J.lo[1] = plane(3); J.n4[1] = (int)(EL / 4);
    for (int i = 0; i < 8; i++) {
        J.src[2 + i] = W[i]; J.hi[2 + i] = wH(i); J.lo[2 + i] = wL(i);
        J.n4[2 + i] = (int)(WEL / 4);
    }
    cvt_split<<<dim3((unsigned)(EL / 4 / 256), 10), 256>>>(J);

    PArgs<6> P6;
    for (int zi = 0; zi < 6; zi++) {
        const int inp = (zi < 3) ? 0 : 2;
        P6.aH[zi] = plane(inp); P6.aL[zi] = plane(inp + 1);
        P6.bH[zi] = wH(zi);     P6.bL[zi] = wL(zi);
        P6.bias[zi] = Bv[zi];
        P6.oH[zi] = plane(4 + 2 * zi); P6.oL[zi] = plane(5 + 2 * zi);
        P6.C[zi] = nullptr;
    }
    cudaFuncSetAttribute((const void*)proj_gemm<6, true>,
                         cudaFuncAttributeMaxDynamicSharedMemorySize, 65536);
    proj_gemm<6, true><<<dim3(4, 64, 6), 256, 65536>>>(P6);

    transpose_v_bf<<<dim3(32, 2, 128), dim3(32, 8)>>>(
        plane(8), plane(9), plane(14), plane(15),
        plane(16), plane(17), plane(18), plane(19));

    StatArgs SA;
    SA.q[0][0] = plane(4);  SA.q[0][1] = plane(5);
    SA.k[0][0] = plane(6);  SA.k[0][1] = plane(7);
    SA.q[1][0] = plane(10); SA.q[1][1] = plane(11);
    SA.k[1][0] = plane(12); SA.k[1][1] = plane(13);
    SA.M[0] = mR; SA.D[0] = dR; SA.M[1] = mF; SA.D[1] = dF;
    cudaFuncSetAttribute((const void*)fa_stats,
                         cudaFuncAttributeMaxDynamicSharedMemorySize, 98304);
    fa_stats<<<dim3(8, 64, 2), 256, 98304>>>(SA);

    cudaFuncSetAttribute((const void*)fa_apply,
                         cudaFuncAttributeMaxDynamicSharedMemorySize, 196608);
    fa_apply<<<dim3(8, 64), 256, 196608>>>(
        plane(4), plane(5), plane(6), plane(7),
        plane(10), plane(11), plane(12), plane(13),
        plane(16), plane(17), plane(18), plane(19),
        mR, dR, mF, dF,
        plane(20), plane(21), plane(22), plane(23));

    float* out = (float*)d_out;
    PArgs<2> P2;
    P2.aH[0] = plane(20); P2.aL[0] = plane(21);
    P2.bH[0] = wH(6);     P2.bL[0] = wL(6);
    P2.bias[0] = Bv[6];   P2.C[0] = out;
    P2.oH[0] = nullptr;   P2.oL[0] = nullptr;
    P2.aH[1] = plane(22); P2.aL[1] = plane(23);
    P2.bH[1] = wH(7);     P2.bL[1] = wL(7);
    P2.bias[1] = Bv[7];   P2.C[1] = out + SL;
    P2.oH[1] = nullptr;   P2.oL[1] = nullptr;
    cudaFuncSetAttribute((const void*)proj_gemm<2, false>,
                         cudaFuncAttributeMaxDynamicSharedMemorySize, 65536);
    proj_gemm<2, false><<<dim3(4, 64, 2), 256, 65536>>>(P2);
}

// round 14
// speedup vs baseline: 1.5171x; 1.5171x over previous
#include <cuda_runtime.h>
#include <cuda_bf16.h>
#include <cstdint>
#include <cstddef>

#define HN  8
#define DM  512
#define DKH 64
#define BB  8
#define SS  1024
#define MR  (BB * SS)
#define SL  ((size_t)MR * DM)
#define EL  ((size_t)MR * DM)
#define WEL ((size_t)DM * DM)

__device__ __nv_bfloat16 g_bf[24 * EL + 16 * WEL];
__device__ float g_stats[4 * (size_t)65536];

// ---------------------------------------------------------------------------
__device__ __forceinline__ uint32_t smem_u32(const void* p) {
    uint32_t a;
    asm("{ .reg .u64 t; cvta.to.shared.u64 t, %1; cvt.u32.u64 %0, t; }" : "=r"(a) : "l"(p));
    return a;
}
__device__ __forceinline__ void ldmx4(uint32_t* r, uint32_t a) {
    asm volatile("ldmatrix.sync.aligned.m8n8.x4.shared.b16 {%0,%1,%2,%3}, [%4];"
                 : "=r"(r[0]), "=r"(r[1]), "=r"(r[2]), "=r"(r[3]) : "r"(a));
}
__device__ __forceinline__ void ldmx2(uint32_t* r, uint32_t a) {
    asm volatile("ldmatrix.sync.aligned.m8n8.x2.shared.b16 {%0,%1}, [%2];"
                 : "=r"(r[0]), "=r"(r[1]) : "r"(a));
}
__device__ __forceinline__ void mma16816(float* c, const uint32_t* a,
                                         uint32_t b0, uint32_t b1) {
    asm volatile(
        "mma.sync.aligned.m16n8k16.row.col.f32.bf16.bf16.f32 "
        "{%0,%1,%2,%3}, {%4,%5,%6,%7}, {%8,%9}, {%0,%1,%2,%3};"
        : "+f"(c[0]), "+f"(c[1]), "+f"(c[2]), "+f"(c[3])
        : "r"(a[0]), "r"(a[1]), "r"(a[2]), "r"(a[3]), "r"(b0), "r"(b1));
}
__device__ __forceinline__ void cp16(uint32_t dst, const void* src) {
    asm volatile("cp.async.cg.shared.global [%0], [%1], 16;" :: "r"(dst), "l"(src));
}
__device__ __forceinline__ void cp_commit() {
    asm volatile("cp.async.commit_group;" ::: "memory");
}
template <int N>
__device__ __forceinline__ void cp_wait() {
    asm volatile("cp.async.wait_group %0;" :: "n"(N) : "memory");
}
__device__ __forceinline__ uint32_t pkbf2(float x, float y) {
    __nv_bfloat162 t;
    t.x = __float2bfloat16_rn(x);
    t.y = __float2bfloat16_rn(y);
    return *reinterpret_cast<uint32_t*>(&t);
}
__device__ __forceinline__ void split4(float4 v, uint2& hi, uint2& lo) {
    __nv_bfloat16 hx = __float2bfloat16_rn(v.x);
    __nv_bfloat16 hy = __float2bfloat16_rn(v.y);
    __nv_bfloat16 hz = __float2bfloat16_rn(v.z);
    __nv_bfloat16 hw = __float2bfloat16_rn(v.w);
    float rx = v.x - __bfloat162float(hx);
    float ry = v.y - __bfloat162float(hy);
    float rz = v.z - __bfloat162float(hz);
    float rw = v.w - __bfloat162float(hw);
    __nv_bfloat162 h01; h01.x = hx; h01.y = hy;
    __nv_bfloat162 h23; h23.x = hz; h23.y = hw;
    hi.x = *reinterpret_cast<uint32_t*>(&h01);
    hi.y = *reinterpret_cast<uint32_t*>(&h23);
    lo.x = pkbf2(rx, ry);
    lo.y = pkbf2(rz, rw);
}
__device__ __forceinline__ void splitp2(float x, float y, uint32_t& hi, uint32_t& lo) {
    __nv_bfloat16 hx = __float2bfloat16_rn(x);
    __nv_bfloat16 hy = __float2bfloat16_rn(y);
    __nv_bfloat162 h; h.x = hx; h.y = hy;
    hi = *reinterpret_cast<uint32_t*>(&h);
    lo = pkbf2(x - __bfloat162float(hx), y - __bfloat162float(hy));
}

// ---------------------------------------------------------------------------
// One-shot fp32 -> split-bf16 conversion (inputs + weights).
// ---------------------------------------------------------------------------
struct CvtJobs {
    const float* src[10];
    __nv_bfloat16* hi[10];
    __nv_bfloat16* lo[10];
    int n4[10];
};
__global__ void __launch_bounds__(256) cvt_split(CvtJobs J) {
    const int j = blockIdx.y;
    const int idx = blockIdx.x * 256 + threadIdx.x;
    if (idx >= J.n4[j]) return;
    float4 v = ((const float4*)J.src[j])[idx];
    uint2 hi, lo;
    split4(v, hi, lo);
    ((uint2*)J.hi[j])[idx] = hi;
    ((uint2*)J.lo[j])[idx] = lo;
}

// ---------------------------------------------------------------------------
// Split-bf16 NT GEMM, preconverted operands, cp.async double-buffered.
// 256 threads, 8 warps (2x4), warp tile 64x32 (LDS/MMA ratio 0.5).
// Register-lean fragment streaming (B via x2 per-kk, A per-(mb,kk)) +
// __launch_bounds__(256,2) -> 2 CTAs/SM = 16 warps/SM.
// ---------------------------------------------------------------------------
template <int NZ>
struct PArgs {
    const __nv_bfloat16 *aH[NZ], *aL[NZ], *bH[NZ], *bL[NZ];
    const float* bias[NZ];
    __nv_bfloat16 *oH[NZ], *oL[NZ];
    float* C[NZ];
};

template <int NZ, bool OUTBF>
__global__ void __launch_bounds__(256, 2) proj_gemm(PArgs<NZ> P)
{
    extern __shared__ char sm[];
    const uint32_t sb = smem_u32(sm);
    const int tid = threadIdx.x, lane = tid & 31, warp = tid >> 5;
    const int z = blockIdx.z;
    const int m0 = blockIdx.y * 128, n0 = blockIdx.x * 128;

    const __nv_bfloat16* AH = P.aH[z] + (size_t)m0 * DM;
    const __nv_bfloat16* AL = P.aL[z] + (size_t)m0 * DM;
    const __nv_bfloat16* BH = P.bH[z] + (size_t)n0 * DM;
    const __nv_bfloat16* BL = P.bL[z] + (size_t)n0 * DM;

    auto issue = [&](int buf, int k0) {
        const uint32_t base = sb + buf * 32768;
#pragma unroll
        for (int jj = 0; jj < 8; jj++) {
            const int comp = jj >> 1;
            const int ci = tid + 256 * (jj & 1);
            const int row = ci >> 2, ch = ci & 3;
            const uint32_t dst = base + comp * 8192 + row * 64
                                 + ((uint32_t)(ch ^ (row & 3)) << 4);
            const __nv_bfloat16* sp = (comp == 0 ? AH : comp == 1 ? AL
                                       : comp == 2 ? BH : BL);
            cp16(dst, sp + (size_t)row * DM + k0 + ch * 8);
        }
        cp_commit();
    };

    const int wm = warp & 1, wn = warp >> 1;
    const int cHi = lane >> 4;
    uint32_t rowAoff[4]; int rA3[4];
#pragma unroll
    for (int mb = 0; mb < 4; mb++) {
        const int rowA = wm * 64 + mb * 16 + (lane & 15);
        rowAoff[mb] = rowA * 64;
        rA3[mb] = rowA & 3;
    }
    const int bsel = (lane >> 3) & 1;
    uint32_t addrB[4]; int rB3[4];
#pragma unroll
    for (int nb = 0; nb < 4; nb++) {
        const int rowB = wn * 32 + nb * 8 + (lane & 7);
        addrB[nb] = rowB * 64;
        rB3[nb] = rowB & 3;
    }

    float acc[4][4][4];
#pragma unroll
    for (int mb = 0; mb < 4; mb++)
#pragma unroll
        for (int nb = 0; nb < 4; nb++)
#pragma unroll
            for (int r = 0; r < 4; r++) acc[mb][nb][r] = 0.f;

    issue(0, 0);

    const int NSTG = 16;
    for (int s = 0; s < NSTG; s++) {
        if (s + 1 < NSTG) {
            issue((s + 1) & 1, (s + 1) * 32);
            cp_wait<1>();
        } else {
            cp_wait<0>();
        }
        __syncthreads();

        const uint32_t stb = sb + (s & 1) * 32768;
#pragma unroll
        for (int kk = 0; kk < 2; kk++) {
            uint32_t BH2[4][2], BL2[4][2];
#pragma unroll
            for (int nb = 0; nb < 4; nb++) {
                const uint32_t a = stb + 16384 + addrB[nb]
                                   + ((uint32_t)((2 * kk + bsel) ^ rB3[nb]) << 4);
                ldmx2(BH2[nb], a);
                ldmx2(BL2[nb], a + 8192);
            }
#pragma unroll
            for (int mb = 0; mb < 4; mb++) {
                const uint32_t a = stb + rowAoff[mb]
                                   + ((uint32_t)((2 * kk + cHi) ^ rA3[mb]) << 4);
                uint32_t AHf[4], ALf[4];
                ldmx4(AHf, a);
                ldmx4(ALf, a + 8192);
#pragma unroll
                for (int nb = 0; nb < 4; nb++) {
                    mma16816(acc[mb][nb], AHf, BH2[nb][0], BH2[nb][1]);
                    mma16816(acc[mb][nb], AHf, BL2[nb][0], BL2[nb][1]);
                    mma16816(acc[mb][nb], ALf, BH2[nb][0], BH2[nb][1]);
                }
            }
        }
        __syncthreads();
    }

    const int gr = lane >> 2, gc2 = (lane & 3) * 2;
#pragma unroll
    for (int mb = 0; mb < 4; mb++) {
        const int row = m0 + wm * 64 + mb * 16 + gr;
#pragma unroll
        for (int nb = 0; nb < 4; nb++) {
            const int gcol = n0 + wn * 32 + nb * 8 + gc2;
            const float bx = P.bias[z][gcol], by = P.bias[z][gcol + 1];
            const float v0 = acc[mb][nb][0] + bx, v1 = acc[mb][nb][1] + by;
            const float v2 = acc[mb][nb][2] + bx, v3 = acc[mb][nb][3] + by;
            if (OUTBF) {
                uint32_t h, l;
                splitp2(v0, v1, h, l);
                *(uint32_t*)(P.oH[z] + (size_t)row * DM + gcol) = h;
                *(uint32_t*)(P.oL[z] + (size_t)row * DM + gcol) = l;
                splitp2(v2, v3, h, l);
                *(uint32_t*)(P.oH[z] + (size_t)(row + 8) * DM + gcol) = h;
                *(uint32_t*)(P.oL[z] + (size_t)(row + 8) * DM + gcol) = l;
            } else {
                float* C = P.C[z];
                *(float2*)(C + (size_t)row * DM + gcol) = make_float2(v0, v1);
                *(float2*)(C + (size_t)(row + 8) * DM + gcol) = make_float2(v2, v3);
            }
        }
    }
}

// ---------------------------------------------------------------------------
// Per-head split-bf16 V transpose (both streams; zz = stream*64 + z).
// ---------------------------------------------------------------------------
__global__ void __launch_bounds__(256) transpose_v_bf(
    const __nv_bfloat16* vrH, const __nv_bfloat16* vrL,
    const __nv_bfloat16* vfH, const __nv_bfloat16* vfL,
    __nv_bfloat16* vtrH, __nv_bfloat16* vtrL,
    __nv_bfloat16* vtfH, __nv_bfloat16* vtfL)
{
    __shared__ unsigned short t[2][32][33];
    const int zz = blockIdx.z;
    const int str = zz >> 6, z = zz & 63;
    const int zbv = z >> 3, zhv = z & 7;
    const int s0 = blockIdx.x * 32, d0 = blockIdx.y * 32;
    const unsigned short* sH = (const unsigned short*)((str ? vfH : vrH)
                               + (size_t)zbv * SS * DM + zhv * 64);
    const unsigned short* sL = (const unsigned short*)((str ? vfL : vrL)
                               + (size_t)zbv * SS * DM + zhv * 64);
    unsigned short* dH = (unsigned short*)((str ? vtfH : vtrH) + (size_t)z * DKH * SS);
    unsigned short* dL = (unsigned short*)((str ? vtfL : vtrL) + (size_t)z * DKH * SS);
    const int tx = threadIdx.x, ty = threadIdx.y;
    for (int i = ty; i < 32; i += 8) {
        t[0][i][tx] = sH[(size_t)(s0 + i) * DM + d0 + tx];
        t[1][i][tx] = sL[(size_t)(s0 + i) * DM + d0 + tx];
    }
    __syncthreads();
    for (int i = ty; i < 32; i += 8) {
        dH[(size_t)(d0 + i) * SS + s0 + tx] = t[0][tx][i];
        dL[(size_t)(d0 + i) * SS + s0 + tx] = t[1][tx][i];
    }
}

// ---------------------------------------------------------------------------
// cp.async tile stagers (pure copies, swizzled dst).
// ---------------------------------------------------------------------------
__device__ __forceinline__ void cp_tile_rk(uint32_t dh, uint32_t dl,
                                           const __nv_bfloat16* sh,
                                           const __nv_bfloat16* sl, int tid) {
#pragma unroll
    for (int jj = 0; jj < 8; jj++) {
        const int comp = jj >> 2;
        const int ci = tid + 256 * (jj & 3);
        const int row = ci >> 3, ch = ci & 7;
        const uint32_t dst = (comp ? dl : dh) + row * 128
                             + ((uint32_t)(ch ^ (row & 7)) << 4);
        const __nv_bfloat16* src = (comp ? sl : sh);
        cp16(dst, src + (size_t)row * DM + ch * 8);
    }
}
__device__ __forceinline__ void cp_tile_vt(uint32_t dh, uint32_t dl,
                                           const __nv_bfloat16* sh,
                                           const __nv_bfloat16* sl, int tid) {
#pragma unroll
    for (int jj = 0; jj < 8; jj++) {
        const int comp = jj >> 2;
        const int ci = tid + 256 * (jj & 3);
        const int row = ci >> 4, ch = ci & 15;
        const uint32_t dst = (comp ? dl : dh) + row * 256
                             + ((uint32_t)(ch ^ (row & 7)) << 4);
        const __nv_bfloat16* src = (comp ? sl : sh);
        cp16(dst, src + (size_t)row * SS + ch * 8);
    }
}

// S chunk: one warp, 16 q rows x 64 kv cols (cols g*64..+63), full dk=64.
__device__ __forceinline__ void s_tile8(uint32_t qh, uint32_t ql, uint32_t kh, uint32_t kl,
                                        int wr0, int lane, int g, float c[8][4]) {
#pragma unroll
    for (int j = 0; j < 8; j++) { c[j][0] = c[j][1] = c[j][2] = c[j][3] = 0.f; }
    const int ar = wr0 + (lane & 15);
    const uint32_t abase = (uint32_t)ar * 128;
    const int arx = ar & 7;
    const int aC = lane >> 4;
    const int brr = lane & 7, bch = lane >> 3;
#pragma unroll
    for (int half = 0; half < 2; half++) {
        const int cb = half * 4;
        uint32_t AH0[4], AH1[4], AL0[4], AL1[4];
        const uint32_t a0off = abase + ((uint32_t)((cb + aC) ^ arx) << 4);
        const uint32_t a1off = abase + ((uint32_t)((cb + 2 + aC) ^ arx) << 4);
        ldmx4(AH0, qh + a0off);
        ldmx4(AL0, ql + a0off);
        ldmx4(AH1, qh + a1off);
        ldmx4(AL1, ql + a1off);
#pragma unroll
        for (int j = 0; j < 8; j++) {
            const int r = (g * 8 + j) * 8 + brr;
            const uint32_t bb = (uint32_t)r * 128 + ((uint32_t)((cb + bch) ^ (r & 7)) << 4);
            uint32_t BH[4], BL[4];
            ldmx4(BH, kh + bb);
            ldmx4(BL, kl + bb);
            mma16816(c[j], AH0, BH[0], BH[1]);
            mma16816(c[j], AH0, BL[0], BL[1]);
            mma16816(c[j], AL0, BH[0], BH[1]);
            mma16816(c[j], AH1, BH[2], BH[3]);
            mma16816(c[j], AH1, BL[2], BL[3]);
            mma16816(c[j], AL1, BH[2], BH[3]);
        }
    }
}

// ---------------------------------------------------------------------------
// Pass 1: online softmax stats. grid (8 qtiles, 64 z, 2 streams).
// SMEM 96KB -> 2 CTAs/SM.
// ---------------------------------------------------------------------------
struct StatArgs {
    const __nv_bfloat16 *q[2][2], *k[2][2];
    float *M[2], *D[2];
};
__global__ void __launch_bounds__(256) fa_stats(StatArgs A)
{
    extern __shared__ char sm[];
    const uint32_t sb = smem_u32(sm);
    const int tid = threadIdx.x, lane = tid & 31, warp = tid >> 5;
    const int str = blockIdx.z, z = blockIdx.y, zb = z >> 3, zh = z & 7;
    const int q0 = blockIdx.x * 128;

    const __nv_bfloat16* Qh = A.q[str][0] + ((size_t)(zb * SS + q0)) * DM + zh * DKH;
    const __nv_bfloat16* Ql = A.q[str][1] + ((size_t)(zb * SS + q0)) * DM + zh * DKH;
    const __nv_bfloat16* Kh = A.k[str][0] + ((size_t)zb * SS) * DM + zh * DKH;
    const __nv_bfloat16* Kl = A.k[str][1] + ((size_t)zb * SS) * DM + zh * DKH;

    cp_tile_rk(sb, sb + 16384, Qh, Ql, tid);
    cp_commit();
    cp_tile_rk(sb + 32768, sb + 49152, Kh, Kl, tid);
    cp_commit();

    const int wr0 = warp * 16;
    float mr0 = -1e30f, mr1 = -1e30f, dr0 = 0.f, dr1 = 0.f;

    for (int kt = 0; kt < 8; kt++) {
        if (kt + 1 < 8) {
            const uint32_t b = sb + 32768 + ((kt + 1) & 1) * 32768;
            cp_tile_rk(b, b + 16384, Kh + (size_t)(kt + 1) * 128 * DM,
                       Kl + (size_t)(kt + 1) * 128 * DM, tid);
            cp_commit();
            cp_wait<1>();
        } else {
            cp_wait<0>();
        }
        __syncthreads();

        const uint32_t kb = sb + 32768 + (kt & 1) * 32768;
#pragma unroll
        for (int g = 0; g < 2; g++) {
            float c[8][4];
            s_tile8(sb, sb + 16384, kb, kb + 16384, wr0, lane, g, c);
#pragma unroll
            for (int j = 0; j < 8; j++) {
                c[j][0] *= 0.125f; c[j][1] *= 0.125f;
                c[j][2] *= 0.125f; c[j][3] *= 0.125f;
            }
            float m0 = -1e30f, m1 = -1e30f;
#pragma unroll
            for (int j = 0; j < 8; j++) {
                m0 = fmaxf(m0, fmaxf(c[j][0], c[j][1]));
                m1 = fmaxf(m1, fmaxf(c[j][2], c[j][3]));
            }
            m0 = fmaxf(m0, __shfl_xor_sync(0xffffffffu, m0, 1));
            m0 = fmaxf(m0, __shfl_xor_sync(0xffffffffu, m0, 2));
            m1 = fmaxf(m1, __shfl_xor_sync(0xffffffffu, m1, 1));
            m1 = fmaxf(m1, __shfl_xor_sync(0xffffffffu, m1, 2));
            const float M0 = fmaxf(mr0, m0), M1 = fmaxf(mr1, m1);
            float s0 = 0.f, s1 = 0.f;
#pragma unroll
            for (int j = 0; j < 8; j++) {
                s0 += __expf(c[j][0] - M0) + __expf(c[j][1] - M0);
                s1 += __expf(c[j][2] - M1) + __expf(c[j][3] - M1);
            }
            s0 += __shfl_xor_sync(0xffffffffu, s0, 1);
            s0 += __shfl_xor_sync(0xffffffffu, s0, 2);
            s1 += __shfl_xor_sync(0xffffffffu, s1, 1);
            s1 += __shfl_xor_sync(0xffffffffu, s1, 2);
            dr0 = dr0 * __expf(mr0 - M0) + s0; mr0 = M0;
            dr1 = dr1 * __expf(mr1 - M1) + s1; mr1 = M1;
        }
        __syncthreads();
    }

    if ((lane & 3) == 0) {
        const int r0 = q0 + wr0 + (lane >> 2);
        A.M[str][(size_t)z * SS + r0] = mr0;
        A.D[str][(size_t)z * SS + r0] = dr0;
        A.M[str][(size_t)z * SS + r0 + 8] = mr1;
        A.D[str][(size_t)z * SS + r0 + 8] = dr1;
    }
}

// ---------------------------------------------------------------------------
// Pass 2: recompute S both streams, merged P, dual PV; split-bf16 O.
// grid (8 qtiles, 64 z). SMEM 192KB: q 4x16K | K 4x16K | V 4x16K.
// ---------------------------------------------------------------------------
__global__ void __launch_bounds__(256) fa_apply(
    const __nv_bfloat16* qrH, const __nv_bfloat16* qrL,
    const __nv_bfloat16* krH, const __nv_bfloat16* krL,
    const __nv_bfloat16* qfH, const __nv_bfloat16* qfL,
    const __nv_bfloat16* kfH, const __nv_bfloat16* kfL,
    const __nv_bfloat16* vtrH, const __nv_bfloat16* vtrL,
    const __nv_bfloat16* vtfH, const __nv_bfloat16* vtfL,
    const float* __restrict__ gMr, const float* __restrict__ gDr,
    const float* __restrict__ gMf, const float* __restrict__ gDf,
    __nv_bfloat16* orH, __nv_bfloat16* orL,
    __nv_bfloat16* ofH, __nv_bfloat16* ofL)
{
    extern __shared__ char sm[];
    const uint32_t sb = smem_u32(sm);
    const int tid = threadIdx.x, lane = tid & 31, warp = tid >> 5;
    const int z = blockIdx.y, zb = z >> 3, zh = z & 7;
    const int q0 = blockIdx.x * 128;

    const size_t qoff = ((size_t)(zb * SS + q0)) * DM + zh * DKH;
    const size_t koff = ((size_t)zb * SS) * DM + zh * DKH;
    const size_t voff = (size_t)z * DKH * SS;

    cp_tile_rk(sb, sb + 16384, qrH + qoff, qrL + qoff, tid);
    cp_tile_rk(sb + 32768, sb + 49152, qfH + qoff, qfL + qoff, tid);
    cp_commit();

    const int wr0 = warp * 16;
    const int gr = lane >> 2;
    const int r0g = q0 + wr0 + gr;
    const size_t st0 = (size_t)z * SS + r0g;
    const float Mr0 = gMr[st0],        Mr1 = gMr[st0 + 8];
    const float iDr0 = 1.f / gDr[st0], iDr1 = 1.f / gDr[st0 + 8];
    const float Mf0 = gMf[st0],        Mf1 = gMf[st0 + 8];
    const float iDf0 = 1.f / gDf[st0], iDf1 = 1.f / gDf[st0 + 8];

    float accR[8][4], accF[8][4];
#pragma unroll
    for (int nb = 0; nb < 8; nb++)
#pragma unroll
        for (int r = 0; r < 4; r++) { accR[nb][r] = 0.f; accF[nb][r] = 0.f; }

    const uint32_t KB = sb + 65536;
    const uint32_t VB = sb + 131072;

    for (int kt = 0; kt < 8; kt++) {
        const size_t kadd = (size_t)kt * 128 * DM;
        cp_tile_rk(KB, KB + 16384, krH + koff + kadd, krL + koff + kadd, tid);
        cp_tile_rk(KB + 32768, KB + 49152, kfH + koff + kadd, kfL + koff + kadd, tid);
        cp_commit();
        cp_tile_vt(VB, VB + 16384, vtrH + voff + kt * 128, vtrL + voff + kt * 128, tid);
        cp_tile_vt(VB + 32768, VB + 49152, vtfH + voff + kt * 128, vtfL + voff + kt * 128, tid);
        cp_commit();
        cp_wait<1>();
        __syncthreads();

        uint32_t ph[8][4], pl[8][4];
#pragma unroll
        for (int g = 0; g < 2; g++) {
            float cr[8][4], cf[8][4];
            s_tile8(sb, sb + 16384, KB, KB + 16384, wr0, lane, g, cr);
            s_tile8(sb + 32768, sb + 49152, KB + 32768, KB + 49152, wr0, lane, g, cf);
#pragma unroll
            for (int jj = 0; jj < 4; jj++) {
                const int kk = g * 4 + jj;
                const int e0 = 2 * jj, e1 = 2 * jj + 1;
                const float p00 = fmaxf(__expf(cr[e0][0] * 0.125f - Mr0) * iDr0,
                                        __expf(cf[e0][0] * 0.125f - Mf0) * iDf0);
                const float p01 = fmaxf(__expf(cr[e0][1] * 0.125f - Mr0) * iDr0,
                                        __expf(cf[e0][1] * 0.125f - Mf0) * iDf0);
                const float p10 = fmaxf(__expf(cr[e0][2] * 0.125f - Mr1) * iDr1,
                                        __expf(cf[e0][2] * 0.125f - Mf1) * iDf1);
                const float p11 = fmaxf(__expf(cr[e0][3] * 0.125f - Mr1) * iDr1,
                                        __expf(cf[e0][3] * 0.125f - Mf1) * iDf1);
                const float q00 = fmaxf(__expf(cr[e1][0] * 0.125f - Mr0) * iDr0,
                                        __expf(cf[e1][0] * 0.125f - Mf0) * iDf0);
                const float q01 = fmaxf(__expf(cr[e1][1] * 0.125f - Mr0) * iDr0,
                                        __expf(cf[e1][1] * 0.125f - Mf0) * iDf0);
                const float q10 = fmaxf(__expf(cr[e1][2] * 0.125f - Mr1) * iDr1,
                                        __expf(cf[e1][2] * 0.125f - Mf1) * iDf1);
                const float q11 = fmaxf(__expf(cr[e1][3] * 0.125f - Mr1) * iDr1,
                                        __expf(cf[e1][3] * 0.125f - Mf1) * iDf1);
                splitp2(p00, p01, ph[kk][0], pl[kk][0]);
                splitp2(p10, p11, ph[kk][1], pl[kk][1]);
                splitp2(q00, q01, ph[kk][2], pl[kk][2]);
                splitp2(q10, q11, ph[kk][3], pl[kk][3]);
            }
        }

        cp_wait<0>();
        __syncthreads();

        const int brr = lane & 7, bch = lane >> 3;
#pragma unroll
        for (int cb = 0; cb < 16; cb += 4) {
            const int kk = cb >> 1;
#pragma unroll
            for (int nb = 0; nb < 8; nb++) {
                const int r = nb * 8 + brr;
                const uint32_t bb = (uint32_t)r * 256
                                    + ((uint32_t)((cb + bch) ^ (r & 7)) << 4);
                uint32_t BHf[4], BLf[4];
                ldmx4(BHf, VB + bb);
                ldmx4(BLf, VB + 16384 + bb);
                mma16816(accR[nb], ph[kk], BHf[0], BHf[1]);
                mma16816(accR[nb], pl[kk], BHf[0], BHf[1]);
                mma16816(accR[nb], ph[kk], BLf[0], BLf[1]);
                mma16816(accR[nb], ph[kk + 1], BHf[2], BHf[3]);
                mma16816(accR[nb], pl[kk + 1], BHf[2], BHf[3]);
                mma16816(accR[nb], ph[kk + 1], BLf[2], BLf[3]);
                ldmx4(BHf, VB + 32768 + bb);
                ldmx4(BLf, VB + 49152 + bb);
                mma16816(accF[nb], ph[kk], BHf[0], BHf[1]);
                mma16816(accF[nb], pl[kk], BHf[0], BHf[1]);
                mma16816(accF[nb], ph[kk], BLf[0], BLf[1]);
                mma16816(accF[nb], ph[kk + 1], BHf[2], BHf[3]);
                mma16816(accF[nb], pl[kk + 1], BHf[2], BHf[3]);
                mma16816(accF[nb], ph[kk + 1], BLf[2], BLf[3]);
            }
        }
        __syncthreads();
    }

    const int gc2 = (lane & 3) * 2;
    const size_t ro0 = ((size_t)(zb * SS + r0g)) * DM + zh * DKH;
    const size_t ro1 = ro0 + (size_t)8 * DM;
#pragma unroll
    for (int nb = 0; nb < 8; nb++) {
        const int col = nb * 8 + gc2;
        uint32_t h, l;
        splitp2(accR[nb][0], accR[nb][1], h, l);
        *(uint32_t*)(orH + ro0 + col) = h;
        *(uint32_t*)(orL + ro0 + col) = l;
        splitp2(accR[nb][2], accR[nb][3], h, l);
        *(uint32_t*)(orH + ro1 + col) = h;
        *(uint32_t*)(orL + ro1 + col) = l;
        splitp2(accF[nb][0], accF[nb][1], h, l);
        *(uint32_t*)(ofH + ro0 + col) = h;
        *(uint32_t*)(ofL + ro0 + col) = l;
        splitp2(accF[nb][2], accF[nb][3], h, l);
        *(uint32_t*)(ofH + ro1 + col) = h;
        *(uint32_t*)(ofL + ro1 + col) = l;
    }
}

// ---------------------------------------------------------------------------
extern "C" void kernel_launch(void* const* d_in, const int* in_sizes, int n_in,
                              void* d_out, int out_size)
{
    const float* rgb  = (const float*)d_in[0];
    const float* flow = (const float*)d_in[1];
    const float* W[8] = {(const float*)d_in[2],  (const float*)d_in[4],
                         (const float*)d_in[6],  (const float*)d_in[8],
                         (const float*)d_in[10], (const float*)d_in[12],
                         (const float*)d_in[14], (const float*)d_in[16]};
    const float* Bv[8] = {(const float*)d_in[3],  (const float*)d_in[5],
                          (const float*)d_in[7],  (const float*)d_in[9],
                          (const float*)d_in[11], (const float*)d_in[13],
                          (const float*)d_in[15], (const float*)d_in[17]};

    __nv_bfloat16* bf = nullptr;
    float* stats = nullptr;
    cudaGetSymbolAddress((void**)&bf, g_bf);
    cudaGetSymbolAddress((void**)&stats, g_stats);

    auto plane = [&](int i) { return bf + (size_t)i * EL; };
    __nv_bfloat16* wbase = bf + 24 * EL;
    auto wH = [&](int i) { return wbase + (size_t)i * 2 * WEL; };
    auto wL = [&](int i) { return wbase + (size_t)i * 2 * WEL + WEL; };

    float* mR = stats;
    float* dR = stats + 65536;
    float* mF = stats + 2 * (size_t)65536;
    float* dF = stats + 3 * (size_t)65536;

    CvtJobs J;
    J.src[0] = rgb;  J.hi[0] = plane(0); J.lo[0] = plane(1); J.n4[0] = (int)(EL / 4);
    J.src[1] = flow; J.hi[1] = plane(2); J.lo[1] = plane(3); J.n4[1] = (int)(EL / 4);
    for (int i = 0; i < 8; i++) {
        J.src[2 + i] = W[i]; J.hi[2 + i] = wH(i); J.lo[2 + i] = wL(i);
        J.n4[2 + i] = (int)(WEL / 4);
    }
    cvt_split<<<dim3((unsigned)(EL / 4 / 256), 10), 256>>>(J);

    PArgs<6> P6;
    for (int zi = 0; zi < 6; zi++) {
        const int inp = (zi < 3) ? 0 : 2;
        P6.aH[zi] = plane(inp); P6.aL[zi] = plane(inp + 1);
        P6.bH[zi] = wH(zi);     P6.bL[zi] = wL(zi);
        P6.bias[zi] = Bv[zi];
        P6.oH[zi] = plane(4 + 2 * zi); P6.oL[zi] = plane(5 + 2 * zi);
        P6.C[zi] = nullptr;
    }
    cudaFuncSetAttribute((const void*)proj_gemm<6, true>,
                         cudaFuncAttributeMaxDynamicSharedMemorySize, 65536);
    proj_gemm<6, true><<<dim3(4, 64, 6), 256, 65536>>>(P6);

    transpose_v_bf<<<dim3(32, 2, 128), dim3(32, 8)>>>(
        plane(8), plane(9), plane(14), plane(15),
        plane(16), plane(17), plane(18), plane(19));

    StatArgs SA;
    SA.q[0][0] = plane(4);  SA.q[0][1] = plane(5);
    SA.k[0][0] = plane(6);  SA.k[0][1] = plane(7);
    SA.q[1][0] = plane(10); SA.q[1][1] = plane(11);
    SA.k[1][0] = plane(12); SA.k[1][1] = plane(13);
    SA.M[0] = mR; SA.D[0] = dR; SA.M[1] = mF; SA.D[1] = dF;
    cudaFuncSetAttribute((const void*)fa_stats,
                         cudaFuncAttributeMaxDynamicSharedMemorySize, 98304);
    fa_stats<<<dim3(8, 64, 2), 256, 98304>>>(SA);

    cudaFuncSetAttribute((const void*)fa_apply,
                         cudaFuncAttributeMaxDynamicSharedMemorySize, 196608);
    fa_apply<<<dim3(8, 64), 256, 196608>>>(
        plane(4), plane(5), plane(6), plane(7),
        plane(10), plane(11), plane(12), plane(13),
        plane(16), plane(17), plane(18), plane(19),
        mR, dR, mF, dF,
        plane(20), plane(21), plane(22), plane(23));

    float* out = (float*)d_out;
    PArgs<2> P2;
    P2.aH[0] = plane(20); P2.aL[0] = plane(21);
    P2.bH[0] = wH(6);     P2.bL[0] = wL(6);
    P2.bias[0] = Bv[6];   P2.C[0] = out;
    P2.oH[0] = nullptr;   P2.oL[0] = nullptr;
    P2.aH[1] = plane(22); P2.aL[1] = plane(23);
    P2.bH[1] = wH(7);     P2.bL[1] = wL(7);
    P2.bias[1] = Bv[7];   P2.C[1] = out + SL;
    P2.oH[1] = nullptr;   P2.oL[1] = nullptr;
    cudaFuncSetAttribute((const void*)proj_gemm<2, false>,
                         cudaFuncAttributeMaxDynamicSharedMemorySize, 65536);
    proj_gemm<2, false><<<dim3(4, 64, 2), 256, 65536>>>(P2);
}

// round 15
// speedup vs baseline: 1.7307x; 1.1407x over previous
#include <cuda_runtime.h>
#include <cuda_bf16.h>
#include <cuda_fp16.h>
#include <cstdint>
#include <cstddef>

#define HN  8
#define DM  512
#define DKH 64
#define BB  8
#define SS  1024
#define MR  (BB * SS)
#define SL  ((size_t)MR * DM)
#define EL  ((size_t)MR * DM)
#define WEL ((size_t)DM * DM)

__device__ __nv_bfloat16 g_bf[24 * EL + 16 * WEL];
__device__ float g_stats[4 * (size_t)65536];

// ---------------------------------------------------------------------------
__device__ __forceinline__ uint32_t smem_u32(const void* p) {
    uint32_t a;
    asm("{ .reg .u64 t; cvta.to.shared.u64 t, %1; cvt.u32.u64 %0, t; }" : "=r"(a) : "l"(p));
    return a;
}
__device__ __forceinline__ void ldmx4(uint32_t* r, uint32_t a) {
    asm volatile("ldmatrix.sync.aligned.m8n8.x4.shared.b16 {%0,%1,%2,%3}, [%4];"
                 : "=r"(r[0]), "=r"(r[1]), "=r"(r[2]), "=r"(r[3]) : "r"(a));
}
__device__ __forceinline__ void ldmx2(uint32_t* r, uint32_t a) {
    asm volatile("ldmatrix.sync.aligned.m8n8.x2.shared.b16 {%0,%1}, [%2];"
                 : "=r"(r[0]), "=r"(r[1]) : "r"(a));
}
__device__ __forceinline__ void mma16816(float* c, const uint32_t* a,
                                         uint32_t b0, uint32_t b1) {
    asm volatile(
        "mma.sync.aligned.m16n8k16.row.col.f32.bf16.bf16.f32 "
        "{%0,%1,%2,%3}, {%4,%5,%6,%7}, {%8,%9}, {%0,%1,%2,%3};"
        : "+f"(c[0]), "+f"(c[1]), "+f"(c[2]), "+f"(c[3])
        : "r"(a[0]), "r"(a[1]), "r"(a[2]), "r"(a[3]), "r"(b0), "r"(b1));
}
__device__ __forceinline__ void mma16816h(float* c, const uint32_t* a,
                                          uint32_t b0, uint32_t b1) {
    asm volatile(
        "mma.sync.aligned.m16n8k16.row.col.f32.f16.f16.f32 "
        "{%0,%1,%2,%3}, {%4,%5,%6,%7}, {%8,%9}, {%0,%1,%2,%3};"
        : "+f"(c[0]), "+f"(c[1]), "+f"(c[2]), "+f"(c[3])
        : "r"(a[0]), "r"(a[1]), "r"(a[2]), "r"(a[3]), "r"(b0), "r"(b1));
}
__device__ __forceinline__ void cp16(uint32_t dst, const void* src) {
    asm volatile("cp.async.cg.shared.global [%0], [%1], 16;" :: "r"(dst), "l"(src));
}
__device__ __forceinline__ void cp_commit() {
    asm volatile("cp.async.commit_group;" ::: "memory");
}
template <int N>
__device__ __forceinline__ void cp_wait() {
    asm volatile("cp.async.wait_group %0;" :: "n"(N) : "memory");
}
__device__ __forceinline__ uint32_t pkbf2(float x, float y) {
    __nv_bfloat162 t;
    t.x = __float2bfloat16_rn(x);
    t.y = __float2bfloat16_rn(y);
    return *reinterpret_cast<uint32_t*>(&t);
}
__device__ __forceinline__ uint32_t pkh2(float x, float y) {
    __half2 t = __floats2half2_rn(x, y);
    return *reinterpret_cast<uint32_t*>(&t);
}
__device__ __forceinline__ void split4(float4 v, uint2& hi, uint2& lo) {
    __nv_bfloat16 hx = __float2bfloat16_rn(v.x);
    __nv_bfloat16 hy = __float2bfloat16_rn(v.y);
    __nv_bfloat16 hz = __float2bfloat16_rn(v.z);
    __nv_bfloat16 hw = __float2bfloat16_rn(v.w);
    float rx = v.x - __bfloat162float(hx);
    float ry = v.y - __bfloat162float(hy);
    float rz = v.z - __bfloat162float(hz);
    float rw = v.w - __bfloat162float(hw);
    __nv_bfloat162 h01; h01.x = hx; h01.y = hy;
    __nv_bfloat162 h23; h23.x = hz; h23.y = hw;
    hi.x = *reinterpret_cast<uint32_t*>(&h01);
    hi.y = *reinterpret_cast<uint32_t*>(&h23);
    lo.x = pkbf2(rx, ry);
    lo.y = pkbf2(rz, rw);
}
__device__ __forceinline__ void splitp2(float x, float y, uint32_t& hi, uint32_t& lo) {
    __nv_bfloat16 hx = __float2bfloat16_rn(x);
    __nv_bfloat16 hy = __float2bfloat16_rn(y);
    __nv_bfloat162 h; h.x = hx; h.y = hy;
    hi = *reinterpret_cast<uint32_t*>(&h);
    lo = pkbf2(x - __bfloat162float(hx), y - __bfloat162float(hy));
}

// ---------------------------------------------------------------------------
// One-shot fp32 -> split-bf16 conversion (inputs + weights).
// ---------------------------------------------------------------------------
struct CvtJobs {
    const float* src[10];
    __nv_bfloat16* hi[10];
    __nv_bfloat16* lo[10];
    int n4[10];
};
__global__ void __launch_bounds__(256) cvt_split(CvtJobs J) {
    const int j = blockIdx.y;
    const int idx = blockIdx.x * 256 + threadIdx.x;
    if (idx >= J.n4[j]) return;
    float4 v = ((const float4*)J.src[j])[idx];
    uint2 hi, lo;
    split4(v, hi, lo);
    ((uint2*)J.hi[j])[idx] = hi;
    ((uint2*)J.lo[j])[idx] = lo;
}

// ---------------------------------------------------------------------------
// Split-bf16 NT GEMM (round-14 winner: 256 thr, 2 CTAs/SM, reg-lean).
// ---------------------------------------------------------------------------
template <int NZ>
struct PArgs {
    const __nv_bfloat16 *aH[NZ], *aL[NZ], *bH[NZ], *bL[NZ];
    const float* bias[NZ];
    __nv_bfloat16 *oH[NZ], *oL[NZ];
    float* C[NZ];
};

template <int NZ, bool OUTBF>
__global__ void __launch_bounds__(256, 2) proj_gemm(PArgs<NZ> P)
{
    extern __shared__ char sm[];
    const uint32_t sb = smem_u32(sm);
    const int tid = threadIdx.x, lane = tid & 31, warp = tid >> 5;
    const int z = blockIdx.z;
    const int m0 = blockIdx.y * 128, n0 = blockIdx.x * 128;

    const __nv_bfloat16* AH = P.aH[z] + (size_t)m0 * DM;
    const __nv_bfloat16* AL = P.aL[z] + (size_t)m0 * DM;
    const __nv_bfloat16* BH = P.bH[z] + (size_t)n0 * DM;
    const __nv_bfloat16* BL = P.bL[z] + (size_t)n0 * DM;

    auto issue = [&](int buf, int k0) {
        const uint32_t base = sb + buf * 32768;
#pragma unroll
        for (int jj = 0; jj < 8; jj++) {
            const int comp = jj >> 1;
            const int ci = tid + 256 * (jj & 1);
            const int row = ci >> 2, ch = ci & 3;
            const uint32_t dst = base + comp * 8192 + row * 64
                                 + ((uint32_t)(ch ^ (row & 3)) << 4);
            const __nv_bfloat16* sp = (comp == 0 ? AH : comp == 1 ? AL
                                       : comp == 2 ? BH : BL);
            cp16(dst, sp + (size_t)row * DM + k0 + ch * 8);
        }
        cp_commit();
    };

    const int wm = warp & 1, wn = warp >> 1;
    const int cHi = lane >> 4;
    uint32_t rowAoff[4]; int rA3[4];
#pragma unroll
    for (int mb = 0; mb < 4; mb++) {
        const int rowA = wm * 64 + mb * 16 + (lane & 15);
        rowAoff[mb] = rowA * 64;
        rA3[mb] = rowA & 3;
    }
    const int bsel = (lane >> 3) & 1;
    uint32_t addrB[4]; int rB3[4];
#pragma unroll
    for (int nb = 0; nb < 4; nb++) {
        const int rowB = wn * 32 + nb * 8 + (lane & 7);
        addrB[nb] = rowB * 64;
        rB3[nb] = rowB & 3;
    }

    float acc[4][4][4];
#pragma unroll
    for (int mb = 0; mb < 4; mb++)
#pragma unroll
        for (int nb = 0; nb < 4; nb++)
#pragma unroll
            for (int r = 0; r < 4; r++) acc[mb][nb][r] = 0.f;

    issue(0, 0);

    const int NSTG = 16;
    for (int s = 0; s < NSTG; s++) {
        if (s + 1 < NSTG) {
            issue((s + 1) & 1, (s + 1) * 32);
            cp_wait<1>();
        } else {
            cp_wait<0>();
        }
        __syncthreads();

        const uint32_t stb = sb + (s & 1) * 32768;
#pragma unroll
        for (int kk = 0; kk < 2; kk++) {
            uint32_t BH2[4][2], BL2[4][2];
#pragma unroll
            for (int nb = 0; nb < 4; nb++) {
                const uint32_t a = stb + 16384 + addrB[nb]
                                   + ((uint32_t)((2 * kk + bsel) ^ rB3[nb]) << 4);
                ldmx2(BH2[nb], a);
                ldmx2(BL2[nb], a + 8192);
            }
#pragma unroll
            for (int mb = 0; mb < 4; mb++) {
                const uint32_t a = stb + rowAoff[mb]
                                   + ((uint32_t)((2 * kk + cHi) ^ rA3[mb]) << 4);
                uint32_t AHf[4], ALf[4];
                ldmx4(AHf, a);
                ldmx4(ALf, a + 8192);
#pragma unroll
                for (int nb = 0; nb < 4; nb++) {
                    mma16816(acc[mb][nb], AHf, BH2[nb][0], BH2[nb][1]);
                    mma16816(acc[mb][nb], AHf, BL2[nb][0], BL2[nb][1]);
                    mma16816(acc[mb][nb], ALf, BH2[nb][0], BH2[nb][1]);
                }
            }
        }
        __syncthreads();
    }

    const int gr = lane >> 2, gc2 = (lane & 3) * 2;
#pragma unroll
    for (int mb = 0; mb < 4; mb++) {
        const int row = m0 + wm * 64 + mb * 16 + gr;
#pragma unroll
        for (int nb = 0; nb < 4; nb++) {
            const int gcol = n0 + wn * 32 + nb * 8 + gc2;
            const float bx = P.bias[z][gcol], by = P.bias[z][gcol + 1];
            const float v0 = acc[mb][nb][0] + bx, v1 = acc[mb][nb][1] + by;
            const float v2 = acc[mb][nb][2] + bx, v3 = acc[mb][nb][3] + by;
            if (OUTBF) {
                uint32_t h, l;
                splitp2(v0, v1, h, l);
                *(uint32_t*)(P.oH[z] + (size_t)row * DM + gcol) = h;
                *(uint32_t*)(P.oL[z] + (size_t)row * DM + gcol) = l;
                splitp2(v2, v3, h, l);
                *(uint32_t*)(P.oH[z] + (size_t)(row + 8) * DM + gcol) = h;
                *(uint32_t*)(P.oL[z] + (size_t)(row + 8) * DM + gcol) = l;
            } else {
                float* C = P.C[z];
                *(float2*)(C + (size_t)row * DM + gcol) = make_float2(v0, v1);
                *(float2*)(C + (size_t)(row + 8) * DM + gcol) = make_float2(v2, v3);
            }
        }
    }
}

// ---------------------------------------------------------------------------
// Per-head V transpose -> SINGLE fp16 plane per stream (hi+lo recombined).
// ---------------------------------------------------------------------------
__global__ void __launch_bounds__(256) transpose_v_f16(
    const __nv_bfloat16* vrH, const __nv_bfloat16* vrL,
    const __nv_bfloat16* vfH, const __nv_bfloat16* vfL,
    __half* vtr16, __half* vtf16)
{
    __shared__ __half t[32][33];
    const int zz = blockIdx.z;
    const int str = zz >> 6, z = zz & 63;
    const int zbv = z >> 3, zhv = z & 7;
    const int s0 = blockIdx.x * 32, d0 = blockIdx.y * 32;
    const __nv_bfloat16* sH = (str ? vfH : vrH) + (size_t)zbv * SS * DM + zhv * 64;
    const __nv_bfloat16* sL = (str ? vfL : vrL) + (size_t)zbv * SS * DM + zhv * 64;
    __half* d16 = (str ? vtf16 : vtr16) + (size_t)z * DKH * SS;
    const int tx = threadIdx.x, ty = threadIdx.y;
    for (int i = ty; i < 32; i += 8) {
        const size_t o = (size_t)(s0 + i) * DM + d0 + tx;
        const float v = __bfloat162float(sH[o]) + __bfloat162float(sL[o]);
        t[i][tx] = __float2half_rn(v);
    }
    __syncthreads();
    for (int i = ty; i < 32; i += 8)
        d16[(size_t)(d0 + i) * SS + s0 + tx] = t[tx][i];
}

// ---------------------------------------------------------------------------
// cp.async tile stagers.
// ---------------------------------------------------------------------------
__device__ __forceinline__ void cp_tile_rk(uint32_t dh, uint32_t dl,
                                           const __nv_bfloat16* sh,
                                           const __nv_bfloat16* sl, int tid) {
#pragma unroll
    for (int jj = 0; jj < 8; jj++) {
        const int comp = jj >> 2;
        const int ci = tid + 256 * (jj & 3);
        const int row = ci >> 3, ch = ci & 7;
        const uint32_t dst = (comp ? dl : dh) + row * 128
                             + ((uint32_t)(ch ^ (row & 7)) << 4);
        const __nv_bfloat16* src = (comp ? sl : sh);
        cp16(dst, src + (size_t)row * DM + ch * 8);
    }
}
// single-plane V^T tile: 64 rows x 128 halfs (256B rows), src stride SS
__device__ __forceinline__ void cp_tile_v16(uint32_t d, const __half* s, int tid) {
#pragma unroll
    for (int jj = 0; jj < 4; jj++) {
        const int ci = tid + 256 * jj;
        const int row = ci >> 4, ch = ci & 15;
        const uint32_t dst = d + row * 256 + ((uint32_t)(ch ^ (row & 7)) << 4);
        cp16(dst, s + (size_t)row * SS + ch * 8);
    }
}

// S chunk: one warp, 16 q rows x 64 kv cols (cols g*64..+63), full dk=64.
__device__ __forceinline__ void s_tile8(uint32_t qh, uint32_t ql, uint32_t kh, uint32_t kl,
                                        int wr0, int lane, int g, float c[8][4]) {
#pragma unroll
    for (int j = 0; j < 8; j++) { c[j][0] = c[j][1] = c[j][2] = c[j][3] = 0.f; }
    const int ar = wr0 + (lane & 15);
    const uint32_t abase = (uint32_t)ar * 128;
    const int arx = ar & 7;
    const int aC = lane >> 4;
    const int brr = lane & 7, bch = lane >> 3;
#pragma unroll
    for (int half = 0; half < 2; half++) {
        const int cb = half * 4;
        uint32_t AH0[4], AH1[4], AL0[4], AL1[4];
        const uint32_t a0off = abase + ((uint32_t)((cb + aC) ^ arx) << 4);
        const uint32_t a1off = abase + ((uint32_t)((cb + 2 + aC) ^ arx) << 4);
        ldmx4(AH0, qh + a0off);
        ldmx4(AL0, ql + a0off);
        ldmx4(AH1, qh + a1off);
        ldmx4(AL1, ql + a1off);
#pragma unroll
        for (int j = 0; j < 8; j++) {
            const int r = (g * 8 + j) * 8 + brr;
            const uint32_t bb = (uint32_t)r * 128 + ((uint32_t)((cb + bch) ^ (r & 7)) << 4);
            uint32_t BH[4], BL[4];
            ldmx4(BH, kh + bb);
            ldmx4(BL, kl + bb);
            mma16816(c[j], AH0, BH[0], BH[1]);
            mma16816(c[j], AH0, BL[0], BL[1]);
            mma16816(c[j], AL0, BH[0], BH[1]);
            mma16816(c[j], AH1, BH[2], BH[3]);
            mma16816(c[j], AH1, BL[2], BL[3]);
            mma16816(c[j], AL1, BH[2], BH[3]);
        }
    }
}

// ---------------------------------------------------------------------------
// Pass 1: online softmax stats (unchanged). grid (8 qtiles, 64 z, 2 streams).
// ---------------------------------------------------------------------------
struct StatArgs {
    const __nv_bfloat16 *q[2][2], *k[2][2];
    float *M[2], *D[2];
};
__global__ void __launch_bounds__(256) fa_stats(StatArgs A)
{
    extern __shared__ char sm[];
    const uint32_t sb = smem_u32(sm);
    const int tid = threadIdx.x, lane = tid & 31, warp = tid >> 5;
    const int str = blockIdx.z, z = blockIdx.y, zb = z >> 3, zh = z & 7;
    const int q0 = blockIdx.x * 128;

    const __nv_bfloat16* Qh = A.q[str][0] + ((size_t)(zb * SS + q0)) * DM + zh * DKH;
    const __nv_bfloat16* Ql = A.q[str][1] + ((size_t)(zb * SS + q0)) * DM + zh * DKH;
    const __nv_bfloat16* Kh = A.k[str][0] + ((size_t)zb * SS) * DM + zh * DKH;
    const __nv_bfloat16* Kl = A.k[str][1] + ((size_t)zb * SS) * DM + zh * DKH;

    cp_tile_rk(sb, sb + 16384, Qh, Ql, tid);
    cp_commit();
    cp_tile_rk(sb + 32768, sb + 49152, Kh, Kl, tid);
    cp_commit();

    const int wr0 = warp * 16;
    float mr0 = -1e30f, mr1 = -1e30f, dr0 = 0.f, dr1 = 0.f;

    for (int kt = 0; kt < 8; kt++) {
        if (kt + 1 < 8) {
            const uint32_t b = sb + 32768 + ((kt + 1) & 1) * 32768;
            cp_tile_rk(b, b + 16384, Kh + (size_t)(kt + 1) * 128 * DM,
                       Kl + (size_t)(kt + 1) * 128 * DM, tid);
            cp_commit();
            cp_wait<1>();
        } else {
            cp_wait<0>();
        }
        __syncthreads();

        const uint32_t kb = sb + 32768 + (kt & 1) * 32768;
#pragma unroll
        for (int g = 0; g < 2; g++) {
            float c[8][4];
            s_tile8(sb, sb + 16384, kb, kb + 16384, wr0, lane, g, c);
#pragma unroll
            for (int j = 0; j < 8; j++) {
                c[j][0] *= 0.125f; c[j][1] *= 0.125f;
                c[j][2] *= 0.125f; c[j][3] *= 0.125f;
            }
            float m0 = -1e30f, m1 = -1e30f;
#pragma unroll
            for (int j = 0; j < 8; j++) {
                m0 = fmaxf(m0, fmaxf(c[j][0], c[j][1]));
                m1 = fmaxf(m1, fmaxf(c[j][2], c[j][3]));
            }
            m0 = fmaxf(m0, __shfl_xor_sync(0xffffffffu, m0, 1));
            m0 = fmaxf(m0, __shfl_xor_sync(0xffffffffu, m0, 2));
            m1 = fmaxf(m1, __shfl_xor_sync(0xffffffffu, m1, 1));
            m1 = fmaxf(m1, __shfl_xor_sync(0xffffffffu, m1, 2));
            const float M0 = fmaxf(mr0, m0), M1 = fmaxf(mr1, m1);
            float s0 = 0.f, s1 = 0.f;
#pragma unroll
            for (int j = 0; j < 8; j++) {
                s0 += __expf(c[j][0] - M0) + __expf(c[j][1] - M0);
                s1 += __expf(c[j][2] - M1) + __expf(c[j][3] - M1);
            }
            s0 += __shfl_xor_sync(0xffffffffu, s0, 1);
            s0 += __shfl_xor_sync(0xffffffffu, s0, 2);
            s1 += __shfl_xor_sync(0xffffffffu, s1, 1);
            s1 += __shfl_xor_sync(0xffffffffu, s1, 2);
            dr0 = dr0 * __expf(mr0 - M0) + s0; mr0 = M0;
            dr1 = dr1 * __expf(mr1 - M1) + s1; mr1 = M1;
        }
        __syncthreads();
    }

    if ((lane & 3) == 0) {
        const int r0 = q0 + wr0 + (lane >> 2);
        A.M[str][(size_t)z * SS + r0] = mr0;
        A.D[str][(size_t)z * SS + r0] = dr0;
        A.M[str][(size_t)z * SS + r0 + 8] = mr1;
        A.D[str][(size_t)z * SS + r0 + 8] = dr1;
    }
}

// ---------------------------------------------------------------------------
// Pass 2: S both streams (split-bf16), merged P -> fp16, single-product PV
// against fp16 V^T. SMEM 160KB: q 4x16K | K 4x16K | V 2x16K.
// ---------------------------------------------------------------------------
__global__ void __launch_bounds__(256) fa_apply(
    const __nv_bfloat16* qrH, const __nv_bfloat16* qrL,
    const __nv_bfloat16* krH, const __nv_bfloat16* krL,
    const __nv_bfloat16* qfH, const __nv_bfloat16* qfL,
    const __nv_bfloat16* kfH, const __nv_bfloat16* kfL,
    const __half* vtr16, const __half* vtf16,
    const float* __restrict__ gMr, const float* __restrict__ gDr,
    const float* __restrict__ gMf, const float* __restrict__ gDf,
    __nv_bfloat16* orH, __nv_bfloat16* orL,
    __nv_bfloat16* ofH, __nv_bfloat16* ofL)
{
    extern __shared__ char sm[];
    const uint32_t sb = smem_u32(sm);
    const int tid = threadIdx.x, lane = tid & 31, warp = tid >> 5;
    const int z = blockIdx.y, zb = z >> 3, zh = z & 7;
    const int q0 = blockIdx.x * 128;

    const size_t qoff = ((size_t)(zb * SS + q0)) * DM + zh * DKH;
    const size_t koff = ((size_t)zb * SS) * DM + zh * DKH;
    const size_t voff = (size_t)z * DKH * SS;

    cp_tile_rk(sb, sb + 16384, qrH + qoff, qrL + qoff, tid);
    cp_tile_rk(sb + 32768, sb + 49152, qfH + qoff, qfL + qoff, tid);
    cp_commit();

    const int wr0 = warp * 16;
    const int gr = lane >> 2;
    const int r0g = q0 + wr0 + gr;
    const size_t st0 = (size_t)z * SS + r0g;
    const float Mr0 = gMr[st0],        Mr1 = gMr[st0 + 8];
    const float iDr0 = 1.f / gDr[st0], iDr1 = 1.f / gDr[st0 + 8];
    const float Mf0 = gMf[st0],        Mf1 = gMf[st0 + 8];
    const float iDf0 = 1.f / gDf[st0], iDf1 = 1.f / gDf[st0 + 8];

    float accR[8][4], accF[8][4];
#pragma unroll
    for (int nb = 0; nb < 8; nb++)
#pragma unroll
        for (int r = 0; r < 4; r++) { accR[nb][r] = 0.f; accF[nb][r] = 0.f; }

    const uint32_t KB = sb + 65536;     // krh krl kfh kfl (4x16K)
    const uint32_t VB = sb + 131072;    // vr16 vf16 (2x16K)

    for (int kt = 0; kt < 8; kt++) {
        const size_t kadd = (size_t)kt * 128 * DM;
        cp_tile_rk(KB, KB + 16384, krH + koff + kadd, krL + koff + kadd, tid);
        cp_tile_rk(KB + 32768, KB + 49152, kfH + koff + kadd, kfL + koff + kadd, tid);
        cp_commit();
        cp_tile_v16(VB, vtr16 + voff + kt * 128, tid);
        cp_tile_v16(VB + 16384, vtf16 + voff + kt * 128, tid);
        cp_commit();
        cp_wait<1>();          // K ready (V still in flight)
        __syncthreads();

        uint32_t ph[8][4];
#pragma unroll
        for (int g = 0; g < 2; g++) {
            float cr[8][4], cf[8][4];
            s_tile8(sb, sb + 16384, KB, KB + 16384, wr0, lane, g, cr);
            s_tile8(sb + 32768, sb + 49152, KB + 32768, KB + 49152, wr0, lane, g, cf);
#pragma unroll
            for (int jj = 0; jj < 4; jj++) {
                const int kk = g * 4 + jj;
                const int e0 = 2 * jj, e1 = 2 * jj + 1;
                const float p00 = fmaxf(__expf(cr[e0][0] * 0.125f - Mr0) * iDr0,
                                        __expf(cf[e0][0] * 0.125f - Mf0) * iDf0);
                const float p01 = fmaxf(__expf(cr[e0][1] * 0.125f - Mr0) * iDr0,
                                        __expf(cf[e0][1] * 0.125f - Mf0) * iDf0);
                const float p10 = fmaxf(__expf(cr[e0][2] * 0.125f - Mr1) * iDr1,
                                        __expf(cf[e0][2] * 0.125f - Mf1) * iDf1);
                const float p11 = fmaxf(__expf(cr[e0][3] * 0.125f - Mr1) * iDr1,
                                        __expf(cf[e0][3] * 0.125f - Mf1) * iDf1);
                const float q00 = fmaxf(__expf(cr[e1][0] * 0.125f - Mr0) * iDr0,
                                        __expf(cf[e1][0] * 0.125f - Mf0) * iDf0);
                const float q01 = fmaxf(__expf(cr[e1][1] * 0.125f - Mr0) * iDr0,
                                        __expf(cf[e1][1] * 0.125f - Mf0) * iDf0);
                const float q10 = fmaxf(__expf(cr[e1][2] * 0.125f - Mr1) * iDr1,
                                        __expf(cf[e1][2] * 0.125f - Mf1) * iDf1);
                const float q11 = fmaxf(__expf(cr[e1][3] * 0.125f - Mr1) * iDr1,
                                        __expf(cf[e1][3] * 0.125f - Mf1) * iDf1);
                ph[kk][0] = pkh2(p00, p01);
                ph[kk][1] = pkh2(p10, p11);
                ph[kk][2] = pkh2(q00, q01);
                ph[kk][3] = pkh2(q10, q11);
            }
        }

        cp_wait<0>();          // V ready
        __syncthreads();

        const int brr = lane & 7, bch = lane >> 3;
#pragma unroll
        for (int cb = 0; cb < 16; cb += 4) {
            const int kk = cb >> 1;
#pragma unroll
            for (int nb = 0; nb < 8; nb++) {
                const int r = nb * 8 + brr;
                const uint32_t bb = (uint32_t)r * 256
                                    + ((uint32_t)((cb + bch) ^ (r & 7)) << 4);
                uint32_t Vf[4];
                ldmx4(Vf, VB + bb);
                mma16816h(accR[nb], ph[kk],     Vf[0], Vf[1]);
                mma16816h(accR[nb], ph[kk + 1], Vf[2], Vf[3]);
                ldmx4(Vf, VB + 16384 + bb);
                mma16816h(accF[nb], ph[kk],     Vf[0], Vf[1]);
                mma16816h(accF[nb], ph[kk + 1], Vf[2], Vf[3]);
            }
        }
        __syncthreads();
    }

    const int gc2 = (lane & 3) * 2;
    const size_t ro0 = ((size_t)(zb * SS + r0g)) * DM + zh * DKH;
    const size_t ro1 = ro0 + (size_t)8 * DM;
#pragma unroll
    for (int nb = 0; nb < 8; nb++) {
        const int col = nb * 8 + gc2;
        uint32_t h, l;
        splitp2(accR[nb][0], accR[nb][1], h, l);
        *(uint32_t*)(orH + ro0 + col) = h;
        *(uint32_t*)(orL + ro0 + col) = l;
        splitp2(accR[nb][2], accR[nb][3], h, l);
        *(uint32_t*)(orH + ro1 + col) = h;
        *(uint32_t*)(orL + ro1 + col) = l;
        splitp2(accF[nb][0], accF[nb][1], h, l);
        *(uint32_t*)(ofH + ro0 + col) = h;
        *(uint32_t*)(ofL + ro0 + col) = l;
        splitp2(accF[nb][2], accF[nb][3], h, l);
        *(uint32_t*)(ofH + ro1 + col) = h;
        *(uint32_t*)(ofL + ro1 + col) = l;
    }
}

// ---------------------------------------------------------------------------
extern "C" void kernel_launch(void* const* d_in, const int* in_sizes, int n_in,
                              void* d_out, int out_size)
{
    const float* rgb  = (const float*)d_in[0];
    const float* flow = (const float*)d_in[1];
    const float* W[8] = {(const float*)d_in[2],  (const float*)d_in[4],
                         (const float*)d_in[6],  (const float*)d_in[8],
                         (const float*)d_in[10], (const float*)d_in[12],
                         (const float*)d_in[14], (const float*)d_in[16]};
    const float* Bv[8] = {(const float*)d_in[3],  (const float*)d_in[5],
                          (const float*)d_in[7],  (const float*)d_in[9],
                          (const float*)d_in[11], (const float*)d_in[13],
                          (const float*)d_in[15], (const float*)d_in[17]};

    __nv_bfloat16* bf = nullptr;
    float* stats = nullptr;
    cudaGetSymbolAddress((void**)&bf, g_bf);
    cudaGetSymbolAddress((void**)&stats, g_stats);

    auto plane = [&](int i) { return bf + (size_t)i * EL; };
    __nv_bfloat16* wbase = bf + 24 * EL;
    auto wH = [&](int i) { return wbase + (size_t)i * 2 * WEL; };
    auto wL = [&](int i) { return wbase + (size_t)i * 2 * WEL + WEL; };

    float* mR = stats;
    float* dR = stats + 65536;
    float* mF = stats + 2 * (size_t)65536;
    float* dF = stats + 3 * (size_t)65536;

    CvtJobs J;
    J.src[0] = rgb;  J.hi[0] = plane(0); J.lo[0] = plane(1); J.n4[0] = (int)(EL / 4);
    J.src[1] = flow; J.hi[1] = plane(2); J.lo[1] = plane(3); J.n4[1] = (int)(EL / 4);
    for (int i = 0; i < 8; i++) {
        J.src[2 + i] = W[i]; J.hi[2 + i] = wH(i); J.lo[2 + i] = wL(i);
        J.n4[2 + i] = (int)(WEL / 4);
    }
    cvt_split<<<dim3((unsigned)(EL / 4 / 256), 10), 256>>>(J);

    PArgs<6> P6;
    for (int zi = 0; zi < 6; zi++) {
        const int inp = (zi < 3) ? 0 : 2;
        P6.aH[zi] = plane(inp); P6.aL[zi] = plane(inp + 1);
        P6.bH[zi] = wH(zi);     P6.bL[zi] = wL(zi);
        P6.bias[zi] = Bv[zi];
        P6.oH[zi] = plane(4 + 2 * zi); P6.oL[zi] = plane(5 + 2 * zi);
        P6.C[zi] = nullptr;
    }
    cudaFuncSetAttribute((const void*)proj_gemm<6, true>,
                         cudaFuncAttributeMaxDynamicSharedMemorySize, 65536);
    proj_gemm<6, true><<<dim3(4, 64, 6), 256, 65536>>>(P6);

    // V^T fp16 planes: 16 (rgb), 17 (flow)
    transpose_v_f16<<<dim3(32, 2, 128), dim3(32, 8)>>>(
        plane(8), plane(9), plane(14), plane(15),
        (__half*)plane(16), (__half*)plane(17));

    StatArgs SA;
    SA.q[0][0] = plane(4);  SA.q[0][1] = plane(5);
    SA.k[0][0] = plane(6);  SA.k[0][1] = plane(7);
    SA.q[1][0] = plane(10); SA.q[1][1] = plane(11);
    SA.k[1][0] = plane(12); SA.k[1][1] = plane(13);
    SA.M[0] = mR; SA.D[0] = dR; SA.M[1] = mF; SA.D[1] = dF;
    cudaFuncSetAttribute((const void*)fa_stats,
                         cudaFuncAttributeMaxDynamicSharedMemorySize, 98304);
    fa_stats<<<dim3(8, 64, 2), 256, 98304>>>(SA);

    cudaFuncSetAttribute((const void*)fa_apply,
                         cudaFuncAttributeMaxDynamicSharedMemorySize, 163840);
    fa_apply<<<dim3(8, 64), 256, 163840>>>(
        plane(4), plane(5), plane(6), plane(7),
        plane(10), plane(11), plane(12), plane(13),
        (const __half*)plane(16), (const __half*)plane(17),
        mR, dR, mF, dF,
        plane(20), plane(21), plane(22), plane(23));

    float* out = (float*)d_out;
    PArgs<2> P2;
    P2.aH[0] = plane(20); P2.aL[0] = plane(21);
    P2.bH[0] = wH(6);     P2.bL[0] = wL(6);
    P2.bias[0] = Bv[6];   P2.C[0] = out;
    P2.oH[0] = nullptr;   P2.oL[0] = nullptr;
    P2.aH[1] = plane(22); P2.aL[1] = plane(23);
    P2.bH[1] = wH(7);     P2.bL[1] = wL(7);
    P2.bias[1] = Bv[7];   P2.C[1] = out + SL;
    P2.oH[1] = nullptr;   P2.oL[1] = nullptr;
    cudaFuncSetAttribute((const void*)proj_gemm<2, false>,
                         cudaFuncAttributeMaxDynamicSharedMemorySize, 65536);
    proj_gemm<2, false><<<dim3(4, 64, 2), 256, 65536>>>(P2);
}